// round 4
// baseline (speedup 1.0000x reference)
#include <cuda_runtime.h>
#include <cuda_bf16.h>
#include <math.h>
#include <stdint.h>

#define Bb 2
#define Ll 2048
#define Dd 1024
#define LH 8
#define MLEN (Bb * Ll)   // 4096

// ---------------- scratch (bf16 hi/lo pairs, stored as uint16) ----------------
__device__ uint16_t g_xh[MLEN * Dd], g_xl[MLEN * Dd];
__device__ uint16_t g_Wqh[Dd * Dd], g_Wql[Dd * Dd];
__device__ uint16_t g_Wkh[Dd * Dd], g_Wkl[Dd * Dd];
__device__ uint16_t g_Wvh[Dd * Dd], g_Wvl[Dd * Dd];
__device__ uint16_t g_Woh[Dd * Dd], g_Wol[Dd * Dd];
__device__ uint16_t g_Qh[MLEN * Dd], g_Ql[MLEN * Dd];
__device__ uint16_t g_Kh[MLEN * Dd], g_Kl[MLEN * Dd];
__device__ uint16_t g_Vh[MLEN * Dd], g_Vl[MLEN * Dd];
__device__ uint16_t g_Oh[MLEN * Dd], g_Ol[MLEN * Dd];
// softmax stats: per (bh,row): 32 col-tiles of 64 -> (max, sumexp)
__device__ float2 g_bstats[32 * 2048 * 32];
__device__ float2 g_rstats[32 * 2048];

// ---------------- helpers ----------------
__device__ __forceinline__ uint32_t smem_u32(const void* p) {
    return (uint32_t)__cvta_generic_to_shared(p);
}

// split two floats -> packed bf16x2 hi (truncation) + bf16x2 lo (rn of residual)
__device__ __forceinline__ void pack_split2(float x0, float x1, uint32_t& h, uint32_t& l) {
    uint32_t u0 = __float_as_uint(x0), u1 = __float_as_uint(x1);
    h = (u0 >> 16) | (u1 & 0xffff0000u);
    float r0 = x0 - __uint_as_float(u0 & 0xffff0000u);
    float r1 = x1 - __uint_as_float(u1 & 0xffff0000u);
    asm("cvt.rn.bf16x2.f32 %0, %1, %2;" : "=r"(l) : "f"(r1), "f"(r0));
}

__device__ __forceinline__ void split_f4(float4 v, uint2& h, uint2& l) {
    pack_split2(v.x, v.y, h.x, l.x);
    pack_split2(v.z, v.w, h.y, l.y);
}

__device__ __forceinline__ void ldsm_x4(uint32_t addr, uint32_t& r0, uint32_t& r1,
                                        uint32_t& r2, uint32_t& r3) {
    asm volatile("ldmatrix.sync.aligned.m8n8.x4.shared.b16 {%0,%1,%2,%3}, [%4];"
                 : "=r"(r0), "=r"(r1), "=r"(r2), "=r"(r3) : "r"(addr));
}
__device__ __forceinline__ void ldsm_x4_t(uint32_t addr, uint32_t& r0, uint32_t& r1,
                                          uint32_t& r2, uint32_t& r3) {
    asm volatile("ldmatrix.sync.aligned.m8n8.x4.trans.shared.b16 {%0,%1,%2,%3}, [%4];"
                 : "=r"(r0), "=r"(r1), "=r"(r2), "=r"(r3) : "r"(addr));
}

__device__ __forceinline__ void mma_bf16(float* c, const uint32_t* a,
                                         uint32_t b0, uint32_t b1) {
    asm volatile(
        "mma.sync.aligned.m16n8k16.row.col.f32.bf16.bf16.f32 "
        "{%0,%1,%2,%3},{%4,%5,%6,%7},{%8,%9},{%0,%1,%2,%3};"
        : "+f"(c[0]), "+f"(c[1]), "+f"(c[2]), "+f"(c[3])
        : "r"(a[0]), "r"(a[1]), "r"(a[2]), "r"(a[3]), "r"(b0), "r"(b1));
}

// ---------------- pre-split f32 -> bf16 hi/lo ----------------
__global__ void split_kernel(const float4* __restrict__ src, uint2* __restrict__ h,
                             uint2* __restrict__ l, int n4) {
    int i = blockIdx.x * 256 + threadIdx.x;
    if (i < n4) {
        uint2 hh, ll;
        split_f4(src[i], hh, ll);
        h[i] = hh;
        l[i] = ll;
    }
}

// 4 weight matrices split in one launch (z selects)
__global__ void split4_kernel(
    const float4* __restrict__ s0, uint2* h0, uint2* l0,
    const float4* __restrict__ s1, uint2* h1, uint2* l1,
    const float4* __restrict__ s2, uint2* h2, uint2* l2,
    const float4* __restrict__ s3, uint2* h3, uint2* l3, int n4)
{
    int z = blockIdx.z;
    const float4* s = (z == 0) ? s0 : (z == 1) ? s1 : (z == 2) ? s2 : s3;
    uint2* h = (z == 0) ? h0 : (z == 1) ? h1 : (z == 2) ? h2 : h3;
    uint2* l = (z == 0) ? l0 : (z == 1) ? l1 : (z == 2) ? l2 : l3;
    int i = blockIdx.x * 256 + threadIdx.x;
    if (i < n4) {
        uint2 hh, ll;
        split_f4(s[i], hh, ll);
        h[i] = hh;
        l[i] = ll;
    }
}

// ---------------- projection GEMM core ----------------
#define PA 24
#define PBT 264
// C[4096,1024] = A @ W + bias. block 128x256, 8 warps, warp 64x64, kstep 16.
// QKV-fused variant: blockIdx.z selects weight/bias/output; writes split bf16.
__global__ __launch_bounds__(256) void gemm_qkv(
    const uint16_t* __restrict__ Ah, const uint16_t* __restrict__ Al,
    const uint16_t* __restrict__ B0h, const uint16_t* __restrict__ B0l,
    const float* __restrict__ bias0, uint16_t* o0h, uint16_t* o0l,
    const uint16_t* __restrict__ B1h, const uint16_t* __restrict__ B1l,
    const float* __restrict__ bias1, uint16_t* o1h, uint16_t* o1l,
    const uint16_t* __restrict__ B2h, const uint16_t* __restrict__ B2l,
    const float* __restrict__ bias2, uint16_t* o2h, uint16_t* o2l)
{
    const int N = 1024, K = 1024;
    int z = blockIdx.z;
    const uint16_t* Bh = (z == 0) ? B0h : (z == 1) ? B1h : B2h;
    const uint16_t* Bl = (z == 0) ? B0l : (z == 1) ? B1l : B2l;
    const float* bias  = (z == 0) ? bias0 : (z == 1) ? bias1 : bias2;
    uint16_t* outH     = (z == 0) ? o0h : (z == 1) ? o1h : o2h;
    uint16_t* outL     = (z == 0) ? o0l : (z == 1) ? o1l : o2l;

    __shared__ __align__(16) uint16_t Ash[128 * PA], Asl[128 * PA];
    __shared__ __align__(16) uint16_t Bsh[16 * PBT], Bsl[16 * PBT];

    int tid = threadIdx.x, lane = tid & 31, wid = tid >> 5;
    int rowBase = blockIdx.y * 128, colBase = blockIdx.x * 256;
    int m0 = (wid >> 2) * 64, n0 = (wid & 3) * 64;

    int ar = tid >> 1, asel = (tid & 1) * 8;
    int bk = tid >> 5, bs = (tid & 31) * 8;

    float c[4][8][4];
    #pragma unroll
    for (int i = 0; i < 4; i++)
        #pragma unroll
        for (int j = 0; j < 8; j++)
            #pragma unroll
            for (int q = 0; q < 4; q++) c[i][j][q] = 0.f;

    uint32_t sAh = smem_u32(Ash), sAl = smem_u32(Asl);
    uint32_t sBh = smem_u32(Bsh), sBl = smem_u32(Bsl);
    uint32_t aoff = (((m0 + (lane & 15)) * PA) + (lane >> 4) * 8) * 2;
    uint32_t boff = ((((lane & 7) + ((lane >> 3) & 1) * 8) * PBT) +
                     n0 + (lane >> 4) * 8) * 2;

    size_t aRow = (size_t)(rowBase + ar) * K;

    uint4 rah, ral, rbh0, rbh1, rbl0, rbl1;
    rah  = *(const uint4*)&Ah[aRow + asel];
    ral  = *(const uint4*)&Al[aRow + asel];
    rbh0 = *(const uint4*)&Bh[(size_t)bk * N + colBase + bs];
    rbh1 = *(const uint4*)&Bh[(size_t)(bk + 8) * N + colBase + bs];
    rbl0 = *(const uint4*)&Bl[(size_t)bk * N + colBase + bs];
    rbl1 = *(const uint4*)&Bl[(size_t)(bk + 8) * N + colBase + bs];

    const int NK = K / 16;
    for (int ks = 0; ks < NK; ks++) {
        *(uint4*)&Ash[ar * PA + asel] = rah;
        *(uint4*)&Asl[ar * PA + asel] = ral;
        *(uint4*)&Bsh[bk * PBT + bs] = rbh0;
        *(uint4*)&Bsh[(bk + 8) * PBT + bs] = rbh1;
        *(uint4*)&Bsl[bk * PBT + bs] = rbl0;
        *(uint4*)&Bsl[(bk + 8) * PBT + bs] = rbl1;
        __syncthreads();

        if (ks + 1 < NK) {
            int k0 = (ks + 1) * 16;
            rah  = *(const uint4*)&Ah[aRow + k0 + asel];
            ral  = *(const uint4*)&Al[aRow + k0 + asel];
            rbh0 = *(const uint4*)&Bh[(size_t)(k0 + bk) * N + colBase + bs];
            rbh1 = *(const uint4*)&Bh[(size_t)(k0 + bk + 8) * N + colBase + bs];
            rbl0 = *(const uint4*)&Bl[(size_t)(k0 + bk) * N + colBase + bs];
            rbl1 = *(const uint4*)&Bl[(size_t)(k0 + bk + 8) * N + colBase + bs];
        }

        uint32_t afh[4][4], afl[4][4];
        #pragma unroll
        for (int i = 0; i < 4; i++) {
            ldsm_x4(sAh + aoff + i * 768, afh[i][0], afh[i][1], afh[i][2], afh[i][3]);
            ldsm_x4(sAl + aoff + i * 768, afl[i][0], afl[i][1], afl[i][2], afl[i][3]);
        }
        #pragma unroll
        for (int j = 0; j < 4; j++) {
            uint32_t bh0, bh1, bh2, bh3, bl0, bl1, bl2, bl3;
            ldsm_x4_t(sBh + boff + j * 32, bh0, bh1, bh2, bh3);
            ldsm_x4_t(sBl + boff + j * 32, bl0, bl1, bl2, bl3);
            #pragma unroll
            for (int i = 0; i < 4; i++) {
                mma_bf16(c[i][2 * j], afh[i], bh0, bh1);
                mma_bf16(c[i][2 * j], afh[i], bl0, bl1);
                mma_bf16(c[i][2 * j], afl[i], bh0, bh1);
                mma_bf16(c[i][2 * j + 1], afh[i], bh2, bh3);
                mma_bf16(c[i][2 * j + 1], afh[i], bl2, bl3);
                mma_bf16(c[i][2 * j + 1], afl[i], bh2, bh3);
            }
        }
        __syncthreads();
    }

    int r = lane >> 2, cl2 = (lane & 3) * 2;
    #pragma unroll
    for (int i = 0; i < 4; i++) {
        int row = rowBase + m0 + i * 16 + r;
        #pragma unroll
        for (int j = 0; j < 8; j++) {
            int col = colBase + n0 + j * 8 + cl2;
            float b0 = bias[col], b1 = bias[col + 1];
            uint32_t hh, ll;
            pack_split2(c[i][j][0] + b0, c[i][j][1] + b1, hh, ll);
            *(uint32_t*)&outH[(size_t)row * N + col] = hh;
            *(uint32_t*)&outL[(size_t)row * N + col] = ll;
            pack_split2(c[i][j][2] + b0, c[i][j][3] + b1, hh, ll);
            *(uint32_t*)&outH[(size_t)(row + 8) * N + col] = hh;
            *(uint32_t*)&outL[(size_t)(row + 8) * N + col] = ll;
        }
    }
}

// out-projection: same core, f32 output
__global__ __launch_bounds__(256) void gemm_out(
    const uint16_t* __restrict__ Ah, const uint16_t* __restrict__ Al,
    const uint16_t* __restrict__ Bh, const uint16_t* __restrict__ Bl,
    const float* __restrict__ bias, float* __restrict__ outF)
{
    const int N = 1024, K = 1024;
    __shared__ __align__(16) uint16_t Ash[128 * PA], Asl[128 * PA];
    __shared__ __align__(16) uint16_t Bsh[16 * PBT], Bsl[16 * PBT];

    int tid = threadIdx.x, lane = tid & 31, wid = tid >> 5;
    int rowBase = blockIdx.y * 128, colBase = blockIdx.x * 256;
    int m0 = (wid >> 2) * 64, n0 = (wid & 3) * 64;

    int ar = tid >> 1, asel = (tid & 1) * 8;
    int bk = tid >> 5, bs = (tid & 31) * 8;

    float c[4][8][4];
    #pragma unroll
    for (int i = 0; i < 4; i++)
        #pragma unroll
        for (int j = 0; j < 8; j++)
            #pragma unroll
            for (int q = 0; q < 4; q++) c[i][j][q] = 0.f;

    uint32_t sAh = smem_u32(Ash), sAl = smem_u32(Asl);
    uint32_t sBh = smem_u32(Bsh), sBl = smem_u32(Bsl);
    uint32_t aoff = (((m0 + (lane & 15)) * PA) + (lane >> 4) * 8) * 2;
    uint32_t boff = ((((lane & 7) + ((lane >> 3) & 1) * 8) * PBT) +
                     n0 + (lane >> 4) * 8) * 2;

    size_t aRow = (size_t)(rowBase + ar) * K;

    uint4 rah, ral, rbh0, rbh1, rbl0, rbl1;
    rah  = *(const uint4*)&Ah[aRow + asel];
    ral  = *(const uint4*)&Al[aRow + asel];
    rbh0 = *(const uint4*)&Bh[(size_t)bk * N + colBase + bs];
    rbh1 = *(const uint4*)&Bh[(size_t)(bk + 8) * N + colBase + bs];
    rbl0 = *(const uint4*)&Bl[(size_t)bk * N + colBase + bs];
    rbl1 = *(const uint4*)&Bl[(size_t)(bk + 8) * N + colBase + bs];

    const int NK = K / 16;
    for (int ks = 0; ks < NK; ks++) {
        *(uint4*)&Ash[ar * PA + asel] = rah;
        *(uint4*)&Asl[ar * PA + asel] = ral;
        *(uint4*)&Bsh[bk * PBT + bs] = rbh0;
        *(uint4*)&Bsh[(bk + 8) * PBT + bs] = rbh1;
        *(uint4*)&Bsl[bk * PBT + bs] = rbl0;
        *(uint4*)&Bsl[(bk + 8) * PBT + bs] = rbl1;
        __syncthreads();

        if (ks + 1 < NK) {
            int k0 = (ks + 1) * 16;
            rah  = *(const uint4*)&Ah[aRow + k0 + asel];
            ral  = *(const uint4*)&Al[aRow + k0 + asel];
            rbh0 = *(const uint4*)&Bh[(size_t)(k0 + bk) * N + colBase + bs];
            rbh1 = *(const uint4*)&Bh[(size_t)(k0 + bk + 8) * N + colBase + bs];
            rbl0 = *(const uint4*)&Bl[(size_t)(k0 + bk) * N + colBase + bs];
            rbl1 = *(const uint4*)&Bl[(size_t)(k0 + bk + 8) * N + colBase + bs];
        }

        uint32_t afh[4][4], afl[4][4];
        #pragma unroll
        for (int i = 0; i < 4; i++) {
            ldsm_x4(sAh + aoff + i * 768, afh[i][0], afh[i][1], afh[i][2], afh[i][3]);
            ldsm_x4(sAl + aoff + i * 768, afl[i][0], afl[i][1], afl[i][2], afl[i][3]);
        }
        #pragma unroll
        for (int j = 0; j < 4; j++) {
            uint32_t bh0, bh1, bh2, bh3, bl0, bl1, bl2, bl3;
            ldsm_x4_t(sBh + boff + j * 32, bh0, bh1, bh2, bh3);
            ldsm_x4_t(sBl + boff + j * 32, bl0, bl1, bl2, bl3);
            #pragma unroll
            for (int i = 0; i < 4; i++) {
                mma_bf16(c[i][2 * j], afh[i], bh0, bh1);
                mma_bf16(c[i][2 * j], afh[i], bl0, bl1);
                mma_bf16(c[i][2 * j], afl[i], bh0, bh1);
                mma_bf16(c[i][2 * j + 1], afh[i], bh2, bh3);
                mma_bf16(c[i][2 * j + 1], afh[i], bl2, bl3);
                mma_bf16(c[i][2 * j + 1], afl[i], bh2, bh3);
            }
        }
        __syncthreads();
    }

    int r = lane >> 2, cl2 = (lane & 3) * 2;
    #pragma unroll
    for (int i = 0; i < 4; i++) {
        int row = rowBase + m0 + i * 16 + r;
        #pragma unroll
        for (int j = 0; j < 8; j++) {
            int col = colBase + n0 + j * 8 + cl2;
            float b0 = bias[col], b1 = bias[col + 1];
            *(float2*)&outF[(size_t)row * N + col] =
                make_float2(c[i][j][0] + b0, c[i][j][1] + b1);
            *(float2*)&outF[(size_t)(row + 8) * N + col] =
                make_float2(c[i][j][2] + b0, c[i][j][3] + b1);
        }
    }
}

// ---------------- scores: S = Q K^T * scale, masked write + softmax partials ----
__global__ __launch_bounds__(256) void scores_mma(
    const uint16_t* __restrict__ Qh, const uint16_t* __restrict__ Ql,
    const uint16_t* __restrict__ Kh, const uint16_t* __restrict__ Kl,
    const float* __restrict__ lsc, const float* __restrict__ gsc,
    float* __restrict__ attnL, float* __restrict__ attnG,
    float2* __restrict__ bstats)
{
    int bh = blockIdx.z;
    int b = bh >> 4, h = bh & 15;
    int rowBase = blockIdx.y * 128, colBase = blockIdx.x * 256;
    bool is_local = (h < LH);
    float* dst = is_local ? attnL + (size_t)(b * LH + h) * Ll * Ll
                          : attnG + (size_t)(b * LH + h - LH) * Ll * Ll;
    int tid = threadIdx.x;

    if (is_local && colBase > rowBase + 127) {
        // fully masked: write zeros (this region is final P = 0)
        float4 z4 = make_float4(0.f, 0.f, 0.f, 0.f);
        #pragma unroll
        for (int i = 0; i < 32; i++) {
            int s = tid + i * 256;
            int row = s >> 6, c4 = s & 63;
            *(float4*)&dst[(size_t)(rowBase + row) * Ll + colBase + c4 * 4] = z4;
        }
        return;
    }

    float scale = 0.125f * (is_local ? lsc[0] : gsc[0]);

    __shared__ __align__(16) uint16_t Ash[128 * PA], Asl[128 * PA];
    __shared__ __align__(16) uint16_t Bsh[256 * PA], Bsl[256 * PA];

    int lane = tid & 31, wid = tid >> 5;
    int m0 = (wid >> 2) * 64, n0 = (wid & 3) * 64;

    int ar = tid >> 1, asel = (tid & 1) * 8;
    size_t aRow  = (size_t)(b * Ll + rowBase + ar) * Dd + h * 64;
    size_t bRow0 = (size_t)(b * Ll + colBase + ar) * Dd + h * 64;
    size_t bRow1 = (size_t)(b * Ll + colBase + ar + 128) * Dd + h * 64;

    float c[4][8][4];
    #pragma unroll
    for (int i = 0; i < 4; i++)
        #pragma unroll
        for (int j = 0; j < 8; j++)
            #pragma unroll
            for (int q = 0; q < 4; q++) c[i][j][q] = 0.f;

    uint32_t sAh = smem_u32(Ash), sAl = smem_u32(Asl);
    uint32_t sBh = smem_u32(Bsh), sBl = smem_u32(Bsl);
    uint32_t aoff = (((m0 + (lane & 15)) * PA) + (lane >> 4) * 8) * 2;
    uint32_t boff = (((n0 + (lane & 7) + (lane >> 4) * 8) * PA) +
                     ((lane >> 3) & 1) * 8) * 2;

    uint4 rah, ral, rbh0, rbh1, rbl0, rbl1;
    rah  = *(const uint4*)&Qh[aRow + asel];
    ral  = *(const uint4*)&Ql[aRow + asel];
    rbh0 = *(const uint4*)&Kh[bRow0 + asel];
    rbh1 = *(const uint4*)&Kh[bRow1 + asel];
    rbl0 = *(const uint4*)&Kl[bRow0 + asel];
    rbl1 = *(const uint4*)&Kl[bRow1 + asel];

    const int NK = 4;   // K = 64
    for (int ks = 0; ks < NK; ks++) {
        *(uint4*)&Ash[ar * PA + asel] = rah;
        *(uint4*)&Asl[ar * PA + asel] = ral;
        *(uint4*)&Bsh[ar * PA + asel] = rbh0;
        *(uint4*)&Bsh[(ar + 128) * PA + asel] = rbh1;
        *(uint4*)&Bsl[ar * PA + asel] = rbl0;
        *(uint4*)&Bsl[(ar + 128) * PA + asel] = rbl1;
        __syncthreads();

        if (ks + 1 < NK) {
            int k0 = (ks + 1) * 16;
            rah  = *(const uint4*)&Qh[aRow + k0 + asel];
            ral  = *(const uint4*)&Ql[aRow + k0 + asel];
            rbh0 = *(const uint4*)&Kh[bRow0 + k0 + asel];
            rbh1 = *(const uint4*)&Kh[bRow1 + k0 + asel];
            rbl0 = *(const uint4*)&Kl[bRow0 + k0 + asel];
            rbl1 = *(const uint4*)&Kl[bRow1 + k0 + asel];
        }

        uint32_t afh[4][4], afl[4][4];
        #pragma unroll
        for (int i = 0; i < 4; i++) {
            ldsm_x4(sAh + aoff + i * 768, afh[i][0], afh[i][1], afh[i][2], afh[i][3]);
            ldsm_x4(sAl + aoff + i * 768, afl[i][0], afl[i][1], afl[i][2], afl[i][3]);
        }
        #pragma unroll
        for (int j = 0; j < 4; j++) {
            uint32_t bh0, bh1, bh2, bh3, bl0, bl1, bl2, bl3;
            ldsm_x4(sBh + boff + j * 768, bh0, bh1, bh2, bh3);
            ldsm_x4(sBl + boff + j * 768, bl0, bl1, bl2, bl3);
            #pragma unroll
            for (int i = 0; i < 4; i++) {
                mma_bf16(c[i][2 * j], afh[i], bh0, bh1);
                mma_bf16(c[i][2 * j], afh[i], bl0, bl1);
                mma_bf16(c[i][2 * j], afl[i], bh0, bh1);
                mma_bf16(c[i][2 * j + 1], afh[i], bh2, bh3);
                mma_bf16(c[i][2 * j + 1], afh[i], bl2, bl3);
                mma_bf16(c[i][2 * j + 1], afl[i], bh2, bh3);
            }
        }
        __syncthreads();
    }

    // epilogue: masked S write + per-(row, 64-col-tile) stats via quad reduce
    int r = lane >> 2, cl2 = (lane & 3) * 2;
    int ntile = (colBase + n0) >> 6;
    #pragma unroll
    for (int i = 0; i < 4; i++) {
        #pragma unroll
        for (int half = 0; half < 2; half++) {
            int row = rowBase + m0 + i * 16 + r + half * 8;
            float vv[16];
            float m = -INFINITY;
            #pragma unroll
            for (int j = 0; j < 8; j++) {
                int col = colBase + n0 + j * 8 + cl2;
                float v0 = c[i][j][half * 2 + 0] * scale;
                float v1 = c[i][j][half * 2 + 1] * scale;
                vv[2 * j] = v0;
                vv[2 * j + 1] = v1;
                bool va = !is_local || (col <= row);
                bool vb = !is_local || (col + 1 <= row);
                if (va) m = fmaxf(m, v0);
                if (vb) m = fmaxf(m, v1);
            }
            m = fmaxf(m, __shfl_xor_sync(0xffffffffu, m, 1));
            m = fmaxf(m, __shfl_xor_sync(0xffffffffu, m, 2));
            float s = 0.f;
            if (m > -1e30f) {
                #pragma unroll
                for (int j = 0; j < 8; j++) {
                    int col = colBase + n0 + j * 8 + cl2;
                    bool va = !is_local || (col <= row);
                    bool vb = !is_local || (col + 1 <= row);
                    if (va) s += __expf(vv[2 * j] - m);
                    if (vb) s += __expf(vv[2 * j + 1] - m);
                }
            }
            s += __shfl_xor_sync(0xffffffffu, s, 1);
            s += __shfl_xor_sync(0xffffffffu, s, 2);
            if ((lane & 3) == 0)
                bstats[((size_t)bh * 2048 + row) * 32 + ntile] = make_float2(m, s);
            // masked S write
            #pragma unroll
            for (int j = 0; j < 8; j++) {
                int col = colBase + n0 + j * 8 + cl2;
                bool va = !is_local || (col <= row);
                bool vb = !is_local || (col + 1 <= row);
                *(float2*)&dst[(size_t)row * Ll + col] =
                    make_float2(va ? vv[2 * j] : 0.f, vb ? vv[2 * j + 1] : 0.f);
            }
        }
    }
}

// ---------------- reduce partial stats -> per-row (max, 1/Z) ----------------
__global__ void reduce_stats(const float2* __restrict__ bst, float2* __restrict__ rst) {
    int idx = blockIdx.x * 256 + threadIdx.x;   // 65536 rows total
    int bh = idx >> 11, row = idx & 2047;
    bool is_local = (bh & 15) < LH;
    int jmax = is_local ? (row >> 6) : 31;
    const float2* p = &bst[(size_t)idx * 32];
    float m = -INFINITY;
    for (int j = 0; j <= jmax; j++) m = fmaxf(m, p[j].x);
    float Z = 0.f;
    for (int j = 0; j <= jmax; j++) {
        float2 v = p[j];
        if (v.x > -1e30f) Z += v.y * __expf(v.x - m);
    }
    rst[idx] = make_float2(m, 1.f / Z);
}

// ---------------- AV: normalize S -> P (write P), O = P @ V ----------------
#define PBV 72
__global__ __launch_bounds__(256) void av_mma(
    float* attnL, float* attnG,
    const uint16_t* __restrict__ Vh, const uint16_t* __restrict__ Vl,
    const float2* __restrict__ rst,
    uint16_t* __restrict__ Oh, uint16_t* __restrict__ Ol)
{
    int bh = blockIdx.y;
    int b = bh >> 4, h = bh & 15;
    int rowBase = blockIdx.x * 128;
    bool is_local = (h < LH);

    float* P = is_local ? attnL + (size_t)(b * LH + h) * Ll * Ll
                        : attnG + (size_t)(b * LH + h - LH) * Ll * Ll;
    int kmax = is_local ? (rowBase + 128) : Ll;
    const int NK = kmax / 16;

    __shared__ __align__(16) uint16_t Ash[128 * PA], Asl[128 * PA];
    __shared__ __align__(16) uint16_t Bsh[16 * PBV], Bsl[16 * PBV];

    int tid = threadIdx.x, lane = tid & 31, wid = tid >> 5;
    int m0 = (wid >> 1) * 32, n0 = (wid & 1) * 32;

    int ar = tid >> 1, asel = (tid & 1) * 8;
    int vk = tid & 15, vseg = tid >> 4;

    int rowG = rowBase + ar;
    float2 st = rst[(size_t)bh * 2048 + rowG];
    size_t aRow = (size_t)rowG * Ll;
    size_t vBase = (size_t)(b * Ll) * Dd + h * 64 + vseg * 4;

    float c[2][4][4];
    #pragma unroll
    for (int i = 0; i < 2; i++)
        #pragma unroll
        for (int j = 0; j < 4; j++)
            #pragma unroll
            for (int q = 0; q < 4; q++) c[i][j][q] = 0.f;

    uint32_t sAh = smem_u32(Ash), sAl = smem_u32(Asl);
    uint32_t sBh = smem_u32(Bsh), sBl = smem_u32(Bsl);
    uint32_t aoff = (((m0 + (lane & 15)) * PA) + (lane >> 4) * 8) * 2;
    uint32_t boff = ((((lane & 7) + ((lane >> 3) & 1) * 8) * PBV) +
                     n0 + (lane >> 4) * 8) * 2;

    float4 ra0, ra1;
    uint2 rbh, rbl;
    ra0 = *(const float4*)&P[aRow + asel];
    ra1 = *(const float4*)&P[aRow + asel + 4];
    rbh = *(const uint2*)&Vh[vBase + (size_t)vk * Dd];
    rbl = *(const uint2*)&Vl[vBase + (size_t)vk * Dd];

    for (int ks = 0; ks < NK; ks++) {
        int k0 = ks * 16;
        int c0 = k0 + asel;
        // normalize: p = exp(s - m) * invZ, masked for causal heads
        float4 p0, p1;
        p0.x = (!is_local || (c0 + 0 <= rowG)) ? __expf(ra0.x - st.x) * st.y : 0.f;
        p0.y = (!is_local || (c0 + 1 <= rowG)) ? __expf(ra0.y - st.x) * st.y : 0.f;
        p0.z = (!is_local || (c0 + 2 <= rowG)) ? __expf(ra0.z - st.x) * st.y : 0.f;
        p0.w = (!is_local || (c0 + 3 <= rowG)) ? __expf(ra0.w - st.x) * st.y : 0.f;
        p1.x = (!is_local || (c0 + 4 <= rowG)) ? __expf(ra1.x - st.x) * st.y : 0.f;
        p1.y = (!is_local || (c0 + 5 <= rowG)) ? __expf(ra1.y - st.x) * st.y : 0.f;
        p1.z = (!is_local || (c0 + 6 <= rowG)) ? __expf(ra1.z - st.x) * st.y : 0.f;
        p1.w = (!is_local || (c0 + 7 <= rowG)) ? __expf(ra1.w - st.x) * st.y : 0.f;
        // write final P (output)
        *(float4*)&P[aRow + c0] = p0;
        *(float4*)&P[aRow + c0 + 4] = p1;
        // stage split-bf16 P for MMA
        uint2 h0, l0, h1, l1;
        split_f4(p0, h0, l0);
        split_f4(p1, h1, l1);
        *(uint2*)&Ash[ar * PA + asel] = h0;
        *(uint2*)&Ash[ar * PA + asel + 4] = h1;
        *(uint2*)&Asl[ar * PA + asel] = l0;
        *(uint2*)&Asl[ar * PA + asel + 4] = l1;
        *(uint2*)&Bsh[vk * PBV + vseg * 4] = rbh;
        *(uint2*)&Bsl[vk * PBV + vseg * 4] = rbl;
        __syncthreads();

        if (ks + 1 < NK) {
            int kn = (ks + 1) * 16;
            ra0 = *(const float4*)&P[aRow + kn + asel];
            ra1 = *(const float4*)&P[aRow + kn + asel + 4];
            rbh = *(const uint2*)&Vh[vBase + (size_t)(kn + vk) * Dd];
            rbl = *(const uint2*)&Vl[vBase + (size_t)(kn + vk) * Dd];
        }

        uint32_t afh[2][4], afl[2][4];
        #pragma unroll
        for (int i = 0; i < 2; i++) {
            ldsm_x4(sAh + aoff + i * 768, afh[i][0], afh[i][1], afh[i][2], afh[i][3]);
            ldsm_x4(sAl + aoff + i * 768, afl[i][0], afl[i][1], afl[i][2], afl[i][3]);
        }
        #pragma unroll
        for (int j = 0; j < 2; j++) {
            uint32_t bh0, bh1, bh2, bh3, bl0, bl1, bl2, bl3;
            ldsm_x4_t(sBh + boff + j * 32, bh0, bh1, bh2, bh3);
            ldsm_x4_t(sBl + boff + j * 32, bl0, bl1, bl2, bl3);
            #pragma unroll
            for (int i = 0; i < 2; i++) {
                mma_bf16(c[i][2 * j], afh[i], bh0, bh1);
                mma_bf16(c[i][2 * j], afh[i], bl0, bl1);
                mma_bf16(c[i][2 * j], afl[i], bh0, bh1);
                mma_bf16(c[i][2 * j + 1], afh[i], bh2, bh3);
                mma_bf16(c[i][2 * j + 1], afh[i], bl2, bl3);
                mma_bf16(c[i][2 * j + 1], afl[i], bh2, bh3);
            }
        }
        __syncthreads();
    }

    int r = lane >> 2, cl2 = (lane & 3) * 2;
    #pragma unroll
    for (int i = 0; i < 2; i++) {
        int row = rowBase + m0 + i * 16 + r;
        #pragma unroll
        for (int j = 0; j < 4; j++) {
            int col = n0 + j * 8 + cl2;
            size_t off0 = (size_t)(b * Ll + row) * Dd + h * 64 + col;
            size_t off1 = (size_t)(b * Ll + row + 8) * Dd + h * 64 + col;
            uint32_t hh, ll;
            pack_split2(c[i][j][0], c[i][j][1], hh, ll);
            *(uint32_t*)&Oh[off0] = hh;
            *(uint32_t*)&Ol[off0] = ll;
            pack_split2(c[i][j][2], c[i][j][3], hh, ll);
            *(uint32_t*)&Oh[off1] = hh;
            *(uint32_t*)&Ol[off1] = ll;
        }
    }
}

// ---------------- launch ----------------
extern "C" void kernel_launch(void* const* d_in, const int* in_sizes, int n_in,
                              void* d_out, int out_size)
{
    const float* x   = (const float*)d_in[0];
    const float* Wq  = (const float*)d_in[1];
    const float* bq  = (const float*)d_in[2];
    const float* Wk  = (const float*)d_in[3];
    const float* bk  = (const float*)d_in[4];
    const float* Wv  = (const float*)d_in[5];
    const float* bv  = (const float*)d_in[6];
    const float* Wo  = (const float*)d_in[7];
    const float* bo  = (const float*)d_in[8];
    const float* lsc = (const float*)d_in[9];
    const float* gsc = (const float*)d_in[10];

    float* out   = (float*)d_out;
    float* attnL = out + (size_t)MLEN * Dd;
    float* attnG = attnL + (size_t)Bb * LH * Ll * Ll;

    uint16_t *xh, *xl, *Wqh, *Wql, *Wkh, *Wkl, *Wvh, *Wvl, *Woh, *Wol;
    uint16_t *Qh, *Ql, *Kh, *Kl, *Vh, *Vl, *Ohp, *Olp;
    float2 *bst, *rstp;
    cudaGetSymbolAddress((void**)&xh, g_xh);   cudaGetSymbolAddress((void**)&xl, g_xl);
    cudaGetSymbolAddress((void**)&Wqh, g_Wqh); cudaGetSymbolAddress((void**)&Wql, g_Wql);
    cudaGetSymbolAddress((void**)&Wkh, g_Wkh); cudaGetSymbolAddress((void**)&Wkl, g_Wkl);
    cudaGetSymbolAddress((void**)&Wvh, g_Wvh); cudaGetSymbolAddress((void**)&Wvl, g_Wvl);
    cudaGetSymbolAddress((void**)&Woh, g_Woh); cudaGetSymbolAddress((void**)&Wol, g_Wol);
    cudaGetSymbolAddress((void**)&Qh, g_Qh);   cudaGetSymbolAddress((void**)&Ql, g_Ql);
    cudaGetSymbolAddress((void**)&Kh, g_Kh);   cudaGetSymbolAddress((void**)&Kl, g_Kl);
    cudaGetSymbolAddress((void**)&Vh, g_Vh);   cudaGetSymbolAddress((void**)&Vl, g_Vl);
    cudaGetSymbolAddress((void**)&Ohp, g_Oh);  cudaGetSymbolAddress((void**)&Olp, g_Ol);
    cudaGetSymbolAddress((void**)&bst, g_bstats);
    cudaGetSymbolAddress((void**)&rstp, g_rstats);

    int nx4 = MLEN * Dd / 4;
    int nw4 = Dd * Dd / 4;
    split_kernel<<<nx4 / 256, 256>>>((const float4*)x, (uint2*)xh, (uint2*)xl, nx4);
    split4_kernel<<<dim3(nw4 / 256, 1, 4), 256>>>(
        (const float4*)Wq, (uint2*)Wqh, (uint2*)Wql,
        (const float4*)Wk, (uint2*)Wkh, (uint2*)Wkl,
        (const float4*)Wv, (uint2*)Wvh, (uint2*)Wvl,
        (const float4*)Wo, (uint2*)Woh, (uint2*)Wol, nw4);

    gemm_qkv<<<dim3(4, 32, 3), 256>>>(xh, xl,
        Wqh, Wql, bq, Qh, Ql,
        Wkh, Wkl, bk, Kh, Kl,
        Wvh, Wvl, bv, Vh, Vl);

    scores_mma<<<dim3(8, 16, 32), 256>>>(Qh, Ql, Kh, Kl, lsc, gsc, attnL, attnG, bst);
    reduce_stats<<<256, 256>>>(bst, rstp);
    av_mma<<<dim3(16, 32), 256>>>(attnL, attnG, Vh, Vl, rstp, Ohp, Olp);

    gemm_out<<<dim3(4, 32), 256>>>(Ohp, Olp, Woh, Wol, bo, out);
}

// round 5
// speedup vs baseline: 1.0745x; 1.0745x over previous
#include <cuda_runtime.h>
#include <cuda_bf16.h>
#include <math.h>
#include <stdint.h>

#define Bb 2
#define Ll 2048
#define Dd 1024
#define LH 8
#define MLEN (Bb * Ll)   // 4096

// ---------------- scratch (bf16 hi/lo pairs, stored as uint16) ----------------
__device__ uint16_t g_xh[MLEN * Dd], g_xl[MLEN * Dd];
__device__ uint16_t g_Wqh[Dd * Dd], g_Wql[Dd * Dd];
__device__ uint16_t g_Wkh[Dd * Dd], g_Wkl[Dd * Dd];
__device__ uint16_t g_Wvh[Dd * Dd], g_Wvl[Dd * Dd];
__device__ uint16_t g_Woh[Dd * Dd], g_Wol[Dd * Dd];
__device__ uint16_t g_Qh[MLEN * Dd], g_Ql[MLEN * Dd];
__device__ uint16_t g_Kh[MLEN * Dd], g_Kl[MLEN * Dd];
__device__ uint16_t g_Vh[MLEN * Dd], g_Vl[MLEN * Dd];
__device__ uint16_t g_Oh[MLEN * Dd], g_Ol[MLEN * Dd];
// softmax stats: per (bh,row): 32 col-tiles of 64 -> (max, sumexp)
__device__ float2 g_bstats[32 * 2048 * 32];
__device__ float2 g_rstats[32 * 2048];

// ---------------- helpers ----------------
__device__ __forceinline__ uint32_t smem_u32(const void* p) {
    return (uint32_t)__cvta_generic_to_shared(p);
}

__device__ __forceinline__ void pack_split2(float x0, float x1, uint32_t& h, uint32_t& l) {
    uint32_t u0 = __float_as_uint(x0), u1 = __float_as_uint(x1);
    h = (u0 >> 16) | (u1 & 0xffff0000u);
    float r0 = x0 - __uint_as_float(u0 & 0xffff0000u);
    float r1 = x1 - __uint_as_float(u1 & 0xffff0000u);
    asm("cvt.rn.bf16x2.f32 %0, %1, %2;" : "=r"(l) : "f"(r1), "f"(r0));
}

__device__ __forceinline__ void split_f4(float4 v, uint2& h, uint2& l) {
    pack_split2(v.x, v.y, h.x, l.x);
    pack_split2(v.z, v.w, h.y, l.y);
}

__device__ __forceinline__ void ldsm_x4(uint32_t addr, uint32_t& r0, uint32_t& r1,
                                        uint32_t& r2, uint32_t& r3) {
    asm volatile("ldmatrix.sync.aligned.m8n8.x4.shared.b16 {%0,%1,%2,%3}, [%4];"
                 : "=r"(r0), "=r"(r1), "=r"(r2), "=r"(r3) : "r"(addr));
}
__device__ __forceinline__ void ldsm_x4_t(uint32_t addr, uint32_t& r0, uint32_t& r1,
                                          uint32_t& r2, uint32_t& r3) {
    asm volatile("ldmatrix.sync.aligned.m8n8.x4.trans.shared.b16 {%0,%1,%2,%3}, [%4];"
                 : "=r"(r0), "=r"(r1), "=r"(r2), "=r"(r3) : "r"(addr));
}

__device__ __forceinline__ void mma_bf16(float* c, const uint32_t* a,
                                         uint32_t b0, uint32_t b1) {
    asm volatile(
        "mma.sync.aligned.m16n8k16.row.col.f32.bf16.bf16.f32 "
        "{%0,%1,%2,%3},{%4,%5,%6,%7},{%8,%9},{%0,%1,%2,%3};"
        : "+f"(c[0]), "+f"(c[1]), "+f"(c[2]), "+f"(c[3])
        : "r"(a[0]), "r"(a[1]), "r"(a[2]), "r"(a[3]), "r"(b0), "r"(b1));
}

// ---------------- pre-split f32 -> bf16 hi/lo ----------------
__global__ void split_kernel(const float4* __restrict__ src, uint2* __restrict__ h,
                             uint2* __restrict__ l, int n4) {
    int i = blockIdx.x * 256 + threadIdx.x;
    if (i < n4) {
        uint2 hh, ll;
        split_f4(src[i], hh, ll);
        h[i] = hh;
        l[i] = ll;
    }
}

__global__ void split4_kernel(
    const float4* __restrict__ s0, uint2* h0, uint2* l0,
    const float4* __restrict__ s1, uint2* h1, uint2* l1,
    const float4* __restrict__ s2, uint2* h2, uint2* l2,
    const float4* __restrict__ s3, uint2* h3, uint2* l3, int n4)
{
    int z = blockIdx.z;
    const float4* s = (z == 0) ? s0 : (z == 1) ? s1 : (z == 2) ? s2 : s3;
    uint2* h = (z == 0) ? h0 : (z == 1) ? h1 : (z == 2) ? h2 : h3;
    uint2* l = (z == 0) ? l0 : (z == 1) ? l1 : (z == 2) ? l2 : l3;
    int i = blockIdx.x * 256 + threadIdx.x;
    if (i < n4) {
        uint2 hh, ll;
        split_f4(s[i], hh, ll);
        h[i] = hh;
        l[i] = ll;
    }
}

// ---------------- projection GEMM core ----------------
#define PA 24
#define PBT 264
__global__ __launch_bounds__(256) void gemm_qkv(
    const uint16_t* __restrict__ Ah, const uint16_t* __restrict__ Al,
    const uint16_t* __restrict__ B0h, const uint16_t* __restrict__ B0l,
    const float* __restrict__ bias0, uint16_t* o0h, uint16_t* o0l,
    const uint16_t* __restrict__ B1h, const uint16_t* __restrict__ B1l,
    const float* __restrict__ bias1, uint16_t* o1h, uint16_t* o1l,
    const uint16_t* __restrict__ B2h, const uint16_t* __restrict__ B2l,
    const float* __restrict__ bias2, uint16_t* o2h, uint16_t* o2l)
{
    const int N = 1024, K = 1024;
    int z = blockIdx.z;
    const uint16_t* Bh = (z == 0) ? B0h : (z == 1) ? B1h : B2h;
    const uint16_t* Bl = (z == 0) ? B0l : (z == 1) ? B1l : B2l;
    const float* bias  = (z == 0) ? bias0 : (z == 1) ? bias1 : bias2;
    uint16_t* outH     = (z == 0) ? o0h : (z == 1) ? o1h : o2h;
    uint16_t* outL     = (z == 0) ? o0l : (z == 1) ? o1l : o2l;

    __shared__ __align__(16) uint16_t Ash[128 * PA], Asl[128 * PA];
    __shared__ __align__(16) uint16_t Bsh[16 * PBT], Bsl[16 * PBT];

    int tid = threadIdx.x, lane = tid & 31, wid = tid >> 5;
    int rowBase = blockIdx.y * 128, colBase = blockIdx.x * 256;
    int m0 = (wid >> 2) * 64, n0 = (wid & 3) * 64;

    int ar = tid >> 1, asel = (tid & 1) * 8;
    int bk = tid >> 5, bs = (tid & 31) * 8;

    float c[4][8][4];
    #pragma unroll
    for (int i = 0; i < 4; i++)
        #pragma unroll
        for (int j = 0; j < 8; j++)
            #pragma unroll
            for (int q = 0; q < 4; q++) c[i][j][q] = 0.f;

    uint32_t sAh = smem_u32(Ash), sAl = smem_u32(Asl);
    uint32_t sBh = smem_u32(Bsh), sBl = smem_u32(Bsl);
    uint32_t aoff = (((m0 + (lane & 15)) * PA) + (lane >> 4) * 8) * 2;
    uint32_t boff = ((((lane & 7) + ((lane >> 3) & 1) * 8) * PBT) +
                     n0 + (lane >> 4) * 8) * 2;

    size_t aRow = (size_t)(rowBase + ar) * K;

    uint4 rah, ral, rbh0, rbh1, rbl0, rbl1;
    rah  = *(const uint4*)&Ah[aRow + asel];
    ral  = *(const uint4*)&Al[aRow + asel];
    rbh0 = *(const uint4*)&Bh[(size_t)bk * N + colBase + bs];
    rbh1 = *(const uint4*)&Bh[(size_t)(bk + 8) * N + colBase + bs];
    rbl0 = *(const uint4*)&Bl[(size_t)bk * N + colBase + bs];
    rbl1 = *(const uint4*)&Bl[(size_t)(bk + 8) * N + colBase + bs];

    const int NK = K / 16;
    for (int ks = 0; ks < NK; ks++) {
        *(uint4*)&Ash[ar * PA + asel] = rah;
        *(uint4*)&Asl[ar * PA + asel] = ral;
        *(uint4*)&Bsh[bk * PBT + bs] = rbh0;
        *(uint4*)&Bsh[(bk + 8) * PBT + bs] = rbh1;
        *(uint4*)&Bsl[bk * PBT + bs] = rbl0;
        *(uint4*)&Bsl[(bk + 8) * PBT + bs] = rbl1;
        __syncthreads();

        if (ks + 1 < NK) {
            int k0 = (ks + 1) * 16;
            rah  = *(const uint4*)&Ah[aRow + k0 + asel];
            ral  = *(const uint4*)&Al[aRow + k0 + asel];
            rbh0 = *(const uint4*)&Bh[(size_t)(k0 + bk) * N + colBase + bs];
            rbh1 = *(const uint4*)&Bh[(size_t)(k0 + bk + 8) * N + colBase + bs];
            rbl0 = *(const uint4*)&Bl[(size_t)(k0 + bk) * N + colBase + bs];
            rbl1 = *(const uint4*)&Bl[(size_t)(k0 + bk + 8) * N + colBase + bs];
        }

        uint32_t afh[4][4], afl[4][4];
        #pragma unroll
        for (int i = 0; i < 4; i++) {
            ldsm_x4(sAh + aoff + i * 768, afh[i][0], afh[i][1], afh[i][2], afh[i][3]);
            ldsm_x4(sAl + aoff + i * 768, afl[i][0], afl[i][1], afl[i][2], afl[i][3]);
        }
        #pragma unroll
        for (int j = 0; j < 4; j++) {
            uint32_t bh0, bh1, bh2, bh3, bl0, bl1, bl2, bl3;
            ldsm_x4_t(sBh + boff + j * 32, bh0, bh1, bh2, bh3);
            ldsm_x4_t(sBl + boff + j * 32, bl0, bl1, bl2, bl3);
            #pragma unroll
            for (int i = 0; i < 4; i++) {
                mma_bf16(c[i][2 * j], afh[i], bh0, bh1);
                mma_bf16(c[i][2 * j], afh[i], bl0, bl1);
                mma_bf16(c[i][2 * j], afl[i], bh0, bh1);
                mma_bf16(c[i][2 * j + 1], afh[i], bh2, bh3);
                mma_bf16(c[i][2 * j + 1], afh[i], bl2, bl3);
                mma_bf16(c[i][2 * j + 1], afl[i], bh2, bh3);
            }
        }
        __syncthreads();
    }

    int r = lane >> 2, cl2 = (lane & 3) * 2;
    #pragma unroll
    for (int i = 0; i < 4; i++) {
        int row = rowBase + m0 + i * 16 + r;
        #pragma unroll
        for (int j = 0; j < 8; j++) {
            int col = colBase + n0 + j * 8 + cl2;
            float b0 = bias[col], b1 = bias[col + 1];
            uint32_t hh, ll;
            pack_split2(c[i][j][0] + b0, c[i][j][1] + b1, hh, ll);
            *(uint32_t*)&outH[(size_t)row * N + col] = hh;
            *(uint32_t*)&outL[(size_t)row * N + col] = ll;
            pack_split2(c[i][j][2] + b0, c[i][j][3] + b1, hh, ll);
            *(uint32_t*)&outH[(size_t)(row + 8) * N + col] = hh;
            *(uint32_t*)&outL[(size_t)(row + 8) * N + col] = ll;
        }
    }
}

__global__ __launch_bounds__(256) void gemm_out(
    const uint16_t* __restrict__ Ah, const uint16_t* __restrict__ Al,
    const uint16_t* __restrict__ Bh, const uint16_t* __restrict__ Bl,
    const float* __restrict__ bias, float* __restrict__ outF)
{
    const int N = 1024, K = 1024;
    __shared__ __align__(16) uint16_t Ash[128 * PA], Asl[128 * PA];
    __shared__ __align__(16) uint16_t Bsh[16 * PBT], Bsl[16 * PBT];

    int tid = threadIdx.x, lane = tid & 31, wid = tid >> 5;
    int rowBase = blockIdx.y * 128, colBase = blockIdx.x * 256;
    int m0 = (wid >> 2) * 64, n0 = (wid & 3) * 64;

    int ar = tid >> 1, asel = (tid & 1) * 8;
    int bk = tid >> 5, bs = (tid & 31) * 8;

    float c[4][8][4];
    #pragma unroll
    for (int i = 0; i < 4; i++)
        #pragma unroll
        for (int j = 0; j < 8; j++)
            #pragma unroll
            for (int q = 0; q < 4; q++) c[i][j][q] = 0.f;

    uint32_t sAh = smem_u32(Ash), sAl = smem_u32(Asl);
    uint32_t sBh = smem_u32(Bsh), sBl = smem_u32(Bsl);
    uint32_t aoff = (((m0 + (lane & 15)) * PA) + (lane >> 4) * 8) * 2;
    uint32_t boff = ((((lane & 7) + ((lane >> 3) & 1) * 8) * PBT) +
                     n0 + (lane >> 4) * 8) * 2;

    size_t aRow = (size_t)(rowBase + ar) * K;

    uint4 rah, ral, rbh0, rbh1, rbl0, rbl1;
    rah  = *(const uint4*)&Ah[aRow + asel];
    ral  = *(const uint4*)&Al[aRow + asel];
    rbh0 = *(const uint4*)&Bh[(size_t)bk * N + colBase + bs];
    rbh1 = *(const uint4*)&Bh[(size_t)(bk + 8) * N + colBase + bs];
    rbl0 = *(const uint4*)&Bl[(size_t)bk * N + colBase + bs];
    rbl1 = *(const uint4*)&Bl[(size_t)(bk + 8) * N + colBase + bs];

    const int NK = K / 16;
    for (int ks = 0; ks < NK; ks++) {
        *(uint4*)&Ash[ar * PA + asel] = rah;
        *(uint4*)&Asl[ar * PA + asel] = ral;
        *(uint4*)&Bsh[bk * PBT + bs] = rbh0;
        *(uint4*)&Bsh[(bk + 8) * PBT + bs] = rbh1;
        *(uint4*)&Bsl[bk * PBT + bs] = rbl0;
        *(uint4*)&Bsl[(bk + 8) * PBT + bs] = rbl1;
        __syncthreads();

        if (ks + 1 < NK) {
            int k0 = (ks + 1) * 16;
            rah  = *(const uint4*)&Ah[aRow + k0 + asel];
            ral  = *(const uint4*)&Al[aRow + k0 + asel];
            rbh0 = *(const uint4*)&Bh[(size_t)(k0 + bk) * N + colBase + bs];
            rbh1 = *(const uint4*)&Bh[(size_t)(k0 + bk + 8) * N + colBase + bs];
            rbl0 = *(const uint4*)&Bl[(size_t)(k0 + bk) * N + colBase + bs];
            rbl1 = *(const uint4*)&Bl[(size_t)(k0 + bk + 8) * N + colBase + bs];
        }

        uint32_t afh[4][4], afl[4][4];
        #pragma unroll
        for (int i = 0; i < 4; i++) {
            ldsm_x4(sAh + aoff + i * 768, afh[i][0], afh[i][1], afh[i][2], afh[i][3]);
            ldsm_x4(sAl + aoff + i * 768, afl[i][0], afl[i][1], afl[i][2], afl[i][3]);
        }
        #pragma unroll
        for (int j = 0; j < 4; j++) {
            uint32_t bh0, bh1, bh2, bh3, bl0, bl1, bl2, bl3;
            ldsm_x4_t(sBh + boff + j * 32, bh0, bh1, bh2, bh3);
            ldsm_x4_t(sBl + boff + j * 32, bl0, bl1, bl2, bl3);
            #pragma unroll
            for (int i = 0; i < 4; i++) {
                mma_bf16(c[i][2 * j], afh[i], bh0, bh1);
                mma_bf16(c[i][2 * j], afh[i], bl0, bl1);
                mma_bf16(c[i][2 * j], afl[i], bh0, bh1);
                mma_bf16(c[i][2 * j + 1], afh[i], bh2, bh3);
                mma_bf16(c[i][2 * j + 1], afh[i], bl2, bl3);
                mma_bf16(c[i][2 * j + 1], afl[i], bh2, bh3);
            }
        }
        __syncthreads();
    }

    int r = lane >> 2, cl2 = (lane & 3) * 2;
    #pragma unroll
    for (int i = 0; i < 4; i++) {
        int row = rowBase + m0 + i * 16 + r;
        #pragma unroll
        for (int j = 0; j < 8; j++) {
            int col = colBase + n0 + j * 8 + cl2;
            float b0 = bias[col], b1 = bias[col + 1];
            *(float2*)&outF[(size_t)row * N + col] =
                make_float2(c[i][j][0] + b0, c[i][j][1] + b1);
            *(float2*)&outF[(size_t)(row + 8) * N + col] =
                make_float2(c[i][j][2] + b0, c[i][j][3] + b1);
        }
    }
}

// ---------------- scores: 128x128 blocks, warp 32x64, 2 CTAs/SM ----------------
__global__ __launch_bounds__(256, 2) void scores_mma(
    const uint16_t* __restrict__ Qh, const uint16_t* __restrict__ Ql,
    const uint16_t* __restrict__ Kh, const uint16_t* __restrict__ Kl,
    const float* __restrict__ lsc, const float* __restrict__ gsc,
    float* __restrict__ attnL, float* __restrict__ attnG,
    float2* __restrict__ bstats)
{
    int bh = blockIdx.z;
    int b = bh >> 4, h = bh & 15;
    int rowBase = blockIdx.y * 128, colBase = blockIdx.x * 128;
    bool is_local = (h < LH);
    float* dst = is_local ? attnL + (size_t)(b * LH + h) * Ll * Ll
                          : attnG + (size_t)(b * LH + h - LH) * Ll * Ll;
    int tid = threadIdx.x;

    if (is_local && colBase > rowBase) {
        // fully masked: P = 0
        float4 z4 = make_float4(0.f, 0.f, 0.f, 0.f);
        #pragma unroll
        for (int i = 0; i < 16; i++) {
            int s = tid + i * 256;
            int row = s >> 5, c4 = s & 31;
            *(float4*)&dst[(size_t)(rowBase + row) * Ll + colBase + c4 * 4] = z4;
        }
        return;
    }
    bool diag = is_local && (colBase == rowBase);

    float scale = 0.125f * (is_local ? lsc[0] : gsc[0]);

    __shared__ __align__(16) uint16_t Ash[128 * PA], Asl[128 * PA];
    __shared__ __align__(16) uint16_t Bsh[128 * PA], Bsl[128 * PA];

    int lane = tid & 31, wid = tid >> 5;
    int m0 = (wid >> 1) * 32, n0 = (wid & 1) * 64;

    int ar = tid >> 1, asel = (tid & 1) * 8;
    size_t aRow = (size_t)(b * Ll + rowBase + ar) * Dd + h * 64;
    size_t bRow = (size_t)(b * Ll + colBase + ar) * Dd + h * 64;

    float c[2][8][4];
    #pragma unroll
    for (int i = 0; i < 2; i++)
        #pragma unroll
        for (int j = 0; j < 8; j++)
            #pragma unroll
            for (int q = 0; q < 4; q++) c[i][j][q] = 0.f;

    uint32_t sAh = smem_u32(Ash), sAl = smem_u32(Asl);
    uint32_t sBh = smem_u32(Bsh), sBl = smem_u32(Bsl);
    uint32_t aoff = (((m0 + (lane & 15)) * PA) + (lane >> 4) * 8) * 2;
    uint32_t boff = (((n0 + (lane & 7) + (lane >> 4) * 8) * PA) +
                     ((lane >> 3) & 1) * 8) * 2;

    uint4 rah, ral, rbh, rbl;
    rah = *(const uint4*)&Qh[aRow + asel];
    ral = *(const uint4*)&Ql[aRow + asel];
    rbh = *(const uint4*)&Kh[bRow + asel];
    rbl = *(const uint4*)&Kl[bRow + asel];

    const int NK = 4;   // K = 64
    for (int ks = 0; ks < NK; ks++) {
        *(uint4*)&Ash[ar * PA + asel] = rah;
        *(uint4*)&Asl[ar * PA + asel] = ral;
        *(uint4*)&Bsh[ar * PA + asel] = rbh;
        *(uint4*)&Bsl[ar * PA + asel] = rbl;
        __syncthreads();

        if (ks + 1 < NK) {
            int k0 = (ks + 1) * 16;
            rah = *(const uint4*)&Qh[aRow + k0 + asel];
            ral = *(const uint4*)&Ql[aRow + k0 + asel];
            rbh = *(const uint4*)&Kh[bRow + k0 + asel];
            rbl = *(const uint4*)&Kl[bRow + k0 + asel];
        }

        uint32_t afh[2][4], afl[2][4];
        #pragma unroll
        for (int i = 0; i < 2; i++) {
            ldsm_x4(sAh + aoff + i * 768, afh[i][0], afh[i][1], afh[i][2], afh[i][3]);
            ldsm_x4(sAl + aoff + i * 768, afl[i][0], afl[i][1], afl[i][2], afl[i][3]);
        }
        #pragma unroll
        for (int j = 0; j < 4; j++) {
            uint32_t bh0, bh1, bh2, bh3, bl0, bl1, bl2, bl3;
            ldsm_x4(sBh + boff + j * 768, bh0, bh1, bh2, bh3);
            ldsm_x4(sBl + boff + j * 768, bl0, bl1, bl2, bl3);
            #pragma unroll
            for (int i = 0; i < 2; i++) {
                mma_bf16(c[i][2 * j], afh[i], bh0, bh1);
                mma_bf16(c[i][2 * j], afh[i], bl0, bl1);
                mma_bf16(c[i][2 * j], afl[i], bh0, bh1);
                mma_bf16(c[i][2 * j + 1], afh[i], bh2, bh3);
                mma_bf16(c[i][2 * j + 1], afh[i], bl2, bl3);
                mma_bf16(c[i][2 * j + 1], afl[i], bh2, bh3);
            }
        }
        __syncthreads();
    }

    // scale in place
    #pragma unroll
    for (int i = 0; i < 2; i++)
        #pragma unroll
        for (int j = 0; j < 8; j++)
            #pragma unroll
            for (int q = 0; q < 4; q++) c[i][j][q] *= scale;

    int r = lane >> 2, cl2 = (lane & 3) * 2;
    int ntile = (colBase + n0) >> 6;

    if (!diag) {
        // unmasked fast path
        #pragma unroll
        for (int i = 0; i < 2; i++) {
            #pragma unroll
            for (int half = 0; half < 2; half++) {
                int row = rowBase + m0 + i * 16 + r + half * 8;
                float m = -INFINITY;
                #pragma unroll
                for (int j = 0; j < 8; j++) {
                    m = fmaxf(m, fmaxf(c[i][j][half * 2], c[i][j][half * 2 + 1]));
                }
                m = fmaxf(m, __shfl_xor_sync(0xffffffffu, m, 1));
                m = fmaxf(m, __shfl_xor_sync(0xffffffffu, m, 2));
                float s = 0.f;
                #pragma unroll
                for (int j = 0; j < 8; j++) {
                    s += __expf(c[i][j][half * 2] - m);
                    s += __expf(c[i][j][half * 2 + 1] - m);
                }
                s += __shfl_xor_sync(0xffffffffu, s, 1);
                s += __shfl_xor_sync(0xffffffffu, s, 2);
                if ((lane & 3) == 0)
                    bstats[((size_t)bh * 2048 + row) * 32 + ntile] = make_float2(m, s);
                #pragma unroll
                for (int j = 0; j < 8; j++) {
                    *(float2*)&dst[(size_t)row * Ll + colBase + n0 + j * 8 + cl2] =
                        make_float2(c[i][j][half * 2], c[i][j][half * 2 + 1]);
                }
            }
        }
    } else {
        // diagonal block: per-element masks
        #pragma unroll
        for (int i = 0; i < 2; i++) {
            #pragma unroll
            for (int half = 0; half < 2; half++) {
                int row = rowBase + m0 + i * 16 + r + half * 8;
                float m = -INFINITY;
                #pragma unroll
                for (int j = 0; j < 8; j++) {
                    int col = colBase + n0 + j * 8 + cl2;
                    float v0 = c[i][j][half * 2], v1 = c[i][j][half * 2 + 1];
                    m = fmaxf(m, (col <= row) ? v0 : -INFINITY);
                    m = fmaxf(m, (col + 1 <= row) ? v1 : -INFINITY);
                }
                m = fmaxf(m, __shfl_xor_sync(0xffffffffu, m, 1));
                m = fmaxf(m, __shfl_xor_sync(0xffffffffu, m, 2));
                float s = 0.f;
                if (m > -1e30f) {
                    #pragma unroll
                    for (int j = 0; j < 8; j++) {
                        int col = colBase + n0 + j * 8 + cl2;
                        float v0 = c[i][j][half * 2], v1 = c[i][j][half * 2 + 1];
                        s += (col <= row) ? __expf(v0 - m) : 0.f;
                        s += (col + 1 <= row) ? __expf(v1 - m) : 0.f;
                    }
                }
                s += __shfl_xor_sync(0xffffffffu, s, 1);
                s += __shfl_xor_sync(0xffffffffu, s, 2);
                if ((lane & 3) == 0)
                    bstats[((size_t)bh * 2048 + row) * 32 + ntile] = make_float2(m, s);
                #pragma unroll
                for (int j = 0; j < 8; j++) {
                    int col = colBase + n0 + j * 8 + cl2;
                    float v0 = (col <= row) ? c[i][j][half * 2] : 0.f;
                    float v1 = (col + 1 <= row) ? c[i][j][half * 2 + 1] : 0.f;
                    *(float2*)&dst[(size_t)row * Ll + col] = make_float2(v0, v1);
                }
            }
        }
    }
}

// ---------------- reduce partial stats -> per-row (max, 1/Z) ----------------
__global__ void reduce_stats(const float2* __restrict__ bst, float2* __restrict__ rst) {
    int idx = blockIdx.x * 256 + threadIdx.x;   // 65536 rows total
    int bh = idx >> 11, row = idx & 2047;
    bool is_local = (bh & 15) < LH;
    int jmax = is_local ? (row >> 6) : 31;
    const float2* p = &bst[(size_t)idx * 32];
    float m = -INFINITY;
    for (int j = 0; j <= jmax; j++) m = fmaxf(m, p[j].x);
    float Z = 0.f;
    for (int j = 0; j <= jmax; j++) {
        float2 v = p[j];
        if (v.x > -1e30f) Z += v.y * __expf(v.x - m);
    }
    rst[idx] = make_float2(m, 1.f / Z);
}

// ---------------- AV: normalize S -> P (write P), O = P @ V ----------------
#define PBV 72
__global__ __launch_bounds__(256) void av_mma(
    float* attnL, float* attnG,
    const uint16_t* __restrict__ Vh, const uint16_t* __restrict__ Vl,
    const float2* __restrict__ rst,
    uint16_t* __restrict__ Oh, uint16_t* __restrict__ Ol)
{
    int bh = blockIdx.y;
    int b = bh >> 4, h = bh & 15;
    int rowBase = blockIdx.x * 128;
    bool is_local = (h < LH);

    float* P = is_local ? attnL + (size_t)(b * LH + h) * Ll * Ll
                        : attnG + (size_t)(b * LH + h - LH) * Ll * Ll;
    int kmax = is_local ? (rowBase + 128) : Ll;
    const int NK = kmax / 16;
    int fastNK = is_local ? (rowBase >> 4) : NK;

    __shared__ __align__(16) uint16_t Ash[128 * PA], Asl[128 * PA];
    __shared__ __align__(16) uint16_t Bsh[16 * PBV], Bsl[16 * PBV];

    int tid = threadIdx.x, lane = tid & 31, wid = tid >> 5;
    int m0 = (wid >> 1) * 32, n0 = (wid & 1) * 32;

    int ar = tid >> 1, asel = (tid & 1) * 8;
    int vk = tid & 15, vseg = tid >> 4;

    int rowG = rowBase + ar;
    float2 st = rst[(size_t)bh * 2048 + rowG];
    size_t aRow = (size_t)rowG * Ll;
    size_t vBase = (size_t)(b * Ll) * Dd + h * 64 + vseg * 4;

    float c[2][4][4];
    #pragma unroll
    for (int i = 0; i < 2; i++)
        #pragma unroll
        for (int j = 0; j < 4; j++)
            #pragma unroll
            for (int q = 0; q < 4; q++) c[i][j][q] = 0.f;

    uint32_t sAh = smem_u32(Ash), sAl = smem_u32(Asl);
    uint32_t sBh = smem_u32(Bsh), sBl = smem_u32(Bsl);
    uint32_t aoff = (((m0 + (lane & 15)) * PA) + (lane >> 4) * 8) * 2;
    uint32_t boff = ((((lane & 7) + ((lane >> 3) & 1) * 8) * PBV) +
                     n0 + (lane >> 4) * 8) * 2;

    float4 ra0, ra1;
    uint2 rbh, rbl;
    ra0 = *(const float4*)&P[aRow + asel];
    ra1 = *(const float4*)&P[aRow + asel + 4];
    rbh = *(const uint2*)&Vh[vBase + (size_t)vk * Dd];
    rbl = *(const uint2*)&Vl[vBase + (size_t)vk * Dd];

    for (int ks = 0; ks < NK; ks++) {
        int k0 = ks * 16;
        int c0 = k0 + asel;
        float4 p0, p1;
        if (ks < fastNK) {
            // no masks needed
            p0.x = __expf(ra0.x - st.x) * st.y;
            p0.y = __expf(ra0.y - st.x) * st.y;
            p0.z = __expf(ra0.z - st.x) * st.y;
            p0.w = __expf(ra0.w - st.x) * st.y;
            p1.x = __expf(ra1.x - st.x) * st.y;
            p1.y = __expf(ra1.y - st.x) * st.y;
            p1.z = __expf(ra1.z - st.x) * st.y;
            p1.w = __expf(ra1.w - st.x) * st.y;
        } else {
            p0.x = (c0 + 0 <= rowG) ? __expf(ra0.x - st.x) * st.y : 0.f;
            p0.y = (c0 + 1 <= rowG) ? __expf(ra0.y - st.x) * st.y : 0.f;
            p0.z = (c0 + 2 <= rowG) ? __expf(ra0.z - st.x) * st.y : 0.f;
            p0.w = (c0 + 3 <= rowG) ? __expf(ra0.w - st.x) * st.y : 0.f;
            p1.x = (c0 + 4 <= rowG) ? __expf(ra1.x - st.x) * st.y : 0.f;
            p1.y = (c0 + 5 <= rowG) ? __expf(ra1.y - st.x) * st.y : 0.f;
            p1.z = (c0 + 6 <= rowG) ? __expf(ra1.z - st.x) * st.y : 0.f;
            p1.w = (c0 + 7 <= rowG) ? __expf(ra1.w - st.x) * st.y : 0.f;
        }
        // write final P (output)
        *(float4*)&P[aRow + c0] = p0;
        *(float4*)&P[aRow + c0 + 4] = p1;
        // stage split-bf16 P for MMA
        uint2 h0, l0, h1, l1;
        split_f4(p0, h0, l0);
        split_f4(p1, h1, l1);
        *(uint2*)&Ash[ar * PA + asel] = h0;
        *(uint2*)&Ash[ar * PA + asel + 4] = h1;
        *(uint2*)&Asl[ar * PA + asel] = l0;
        *(uint2*)&Asl[ar * PA + asel + 4] = l1;
        *(uint2*)&Bsh[vk * PBV + vseg * 4] = rbh;
        *(uint2*)&Bsl[vk * PBV + vseg * 4] = rbl;
        __syncthreads();

        if (ks + 1 < NK) {
            int kn = (ks + 1) * 16;
            ra0 = *(const float4*)&P[aRow + kn + asel];
            ra1 = *(const float4*)&P[aRow + kn + asel + 4];
            rbh = *(const uint2*)&Vh[vBase + (size_t)(kn + vk) * Dd];
            rbl = *(const uint2*)&Vl[vBase + (size_t)(kn + vk) * Dd];
        }

        uint32_t afh[2][4], afl[2][4];
        #pragma unroll
        for (int i = 0; i < 2; i++) {
            ldsm_x4(sAh + aoff + i * 768, afh[i][0], afh[i][1], afh[i][2], afh[i][3]);
            ldsm_x4(sAl + aoff + i * 768, afl[i][0], afl[i][1], afl[i][2], afl[i][3]);
        }
        #pragma unroll
        for (int j = 0; j < 2; j++) {
            uint32_t bh0, bh1, bh2, bh3, bl0, bl1, bl2, bl3;
            ldsm_x4_t(sBh + boff + j * 32, bh0, bh1, bh2, bh3);
            ldsm_x4_t(sBl + boff + j * 32, bl0, bl1, bl2, bl3);
            #pragma unroll
            for (int i = 0; i < 2; i++) {
                mma_bf16(c[i][2 * j], afh[i], bh0, bh1);
                mma_bf16(c[i][2 * j], afh[i], bl0, bl1);
                mma_bf16(c[i][2 * j], afl[i], bh0, bh1);
                mma_bf16(c[i][2 * j + 1], afh[i], bh2, bh3);
                mma_bf16(c[i][2 * j + 1], afh[i], bl2, bl3);
                mma_bf16(c[i][2 * j + 1], afl[i], bh2, bh3);
            }
        }
        __syncthreads();
    }

    int r = lane >> 2, cl2 = (lane & 3) * 2;
    #pragma unroll
    for (int i = 0; i < 2; i++) {
        int row = rowBase + m0 + i * 16 + r;
        #pragma unroll
        for (int j = 0; j < 4; j++) {
            int col = n0 + j * 8 + cl2;
            size_t off0 = (size_t)(b * Ll + row) * Dd + h * 64 + col;
            size_t off1 = (size_t)(b * Ll + row + 8) * Dd + h * 64 + col;
            uint32_t hh, ll;
            pack_split2(c[i][j][0], c[i][j][1], hh, ll);
            *(uint32_t*)&Oh[off0] = hh;
            *(uint32_t*)&Ol[off0] = ll;
            pack_split2(c[i][j][2], c[i][j][3], hh, ll);
            *(uint32_t*)&Oh[off1] = hh;
            *(uint32_t*)&Ol[off1] = ll;
        }
    }
}

// ---------------- launch ----------------
extern "C" void kernel_launch(void* const* d_in, const int* in_sizes, int n_in,
                              void* d_out, int out_size)
{
    const float* x   = (const float*)d_in[0];
    const float* Wq  = (const float*)d_in[1];
    const float* bq  = (const float*)d_in[2];
    const float* Wk  = (const float*)d_in[3];
    const float* bk  = (const float*)d_in[4];
    const float* Wv  = (const float*)d_in[5];
    const float* bv  = (const float*)d_in[6];
    const float* Wo  = (const float*)d_in[7];
    const float* bo  = (const float*)d_in[8];
    const float* lsc = (const float*)d_in[9];
    const float* gsc = (const float*)d_in[10];

    float* out   = (float*)d_out;
    float* attnL = out + (size_t)MLEN * Dd;
    float* attnG = attnL + (size_t)Bb * LH * Ll * Ll;

    uint16_t *xh, *xl, *Wqh, *Wql, *Wkh, *Wkl, *Wvh, *Wvl, *Woh, *Wol;
    uint16_t *Qh, *Ql, *Kh, *Kl, *Vh, *Vl, *Ohp, *Olp;
    float2 *bst, *rstp;
    cudaGetSymbolAddress((void**)&xh, g_xh);   cudaGetSymbolAddress((void**)&xl, g_xl);
    cudaGetSymbolAddress((void**)&Wqh, g_Wqh); cudaGetSymbolAddress((void**)&Wql, g_Wql);
    cudaGetSymbolAddress((void**)&Wkh, g_Wkh); cudaGetSymbolAddress((void**)&Wkl, g_Wkl);
    cudaGetSymbolAddress((void**)&Wvh, g_Wvh); cudaGetSymbolAddress((void**)&Wvl, g_Wvl);
    cudaGetSymbolAddress((void**)&Woh, g_Woh); cudaGetSymbolAddress((void**)&Wol, g_Wol);
    cudaGetSymbolAddress((void**)&Qh, g_Qh);   cudaGetSymbolAddress((void**)&Ql, g_Ql);
    cudaGetSymbolAddress((void**)&Kh, g_Kh);   cudaGetSymbolAddress((void**)&Kl, g_Kl);
    cudaGetSymbolAddress((void**)&Vh, g_Vh);   cudaGetSymbolAddress((void**)&Vl, g_Vl);
    cudaGetSymbolAddress((void**)&Ohp, g_Oh);  cudaGetSymbolAddress((void**)&Olp, g_Ol);
    cudaGetSymbolAddress((void**)&bst, g_bstats);
    cudaGetSymbolAddress((void**)&rstp, g_rstats);

    int nx4 = MLEN * Dd / 4;
    int nw4 = Dd * Dd / 4;
    split_kernel<<<nx4 / 256, 256>>>((const float4*)x, (uint2*)xh, (uint2*)xl, nx4);
    split4_kernel<<<dim3(nw4 / 256, 1, 4), 256>>>(
        (const float4*)Wq, (uint2*)Wqh, (uint2*)Wql,
        (const float4*)Wk, (uint2*)Wkh, (uint2*)Wkl,
        (const float4*)Wv, (uint2*)Wvh, (uint2*)Wvl,
        (const float4*)Wo, (uint2*)Woh, (uint2*)Wol, nw4);

    gemm_qkv<<<dim3(4, 32, 3), 256>>>(xh, xl,
        Wqh, Wql, bq, Qh, Ql,
        Wkh, Wkl, bk, Kh, Kl,
        Wvh, Wvl, bv, Vh, Vl);

    scores_mma<<<dim3(16, 16, 32), 256>>>(Qh, Ql, Kh, Kl, lsc, gsc, attnL, attnG, bst);
    reduce_stats<<<256, 256>>>(bst, rstp);
    av_mma<<<dim3(16, 32), 256>>>(attnL, attnG, Vh, Vl, rstp, Ohp, Olp);

    gemm_out<<<dim3(4, 32), 256>>>(Ohp, Olp, Woh, Wol, bo, out);
}

// round 6
// speedup vs baseline: 1.0756x; 1.0010x over previous
#include <cuda_runtime.h>
#include <cuda_bf16.h>
#include <math.h>
#include <stdint.h>

#define Bb 2
#define Ll 2048
#define Dd 1024
#define LH 8
#define MLEN (Bb * Ll)   // 4096

// ---------------- scratch (bf16 hi/lo pairs, stored as uint16) ----------------
__device__ uint16_t g_xh[MLEN * Dd], g_xl[MLEN * Dd];
__device__ uint16_t g_Wqh[Dd * Dd], g_Wql[Dd * Dd];
__device__ uint16_t g_Wkh[Dd * Dd], g_Wkl[Dd * Dd];
__device__ uint16_t g_Wvh[Dd * Dd], g_Wvl[Dd * Dd];
__device__ uint16_t g_Woh[Dd * Dd], g_Wol[Dd * Dd];
__device__ uint16_t g_Qh[MLEN * Dd], g_Ql[MLEN * Dd];
__device__ uint16_t g_Kh[MLEN * Dd], g_Kl[MLEN * Dd];
__device__ uint16_t g_Vh[MLEN * Dd], g_Vl[MLEN * Dd];
__device__ uint16_t g_Oh[MLEN * Dd], g_Ol[MLEN * Dd];
__device__ float2 g_bstats[32 * 2048 * 32];
__device__ float2 g_rstats[32 * 2048];

// ---------------- helpers ----------------
__device__ __forceinline__ uint32_t smem_u32(const void* p) {
    return (uint32_t)__cvta_generic_to_shared(p);
}

__device__ __forceinline__ void pack_split2(float x0, float x1, uint32_t& h, uint32_t& l) {
    uint32_t u0 = __float_as_uint(x0), u1 = __float_as_uint(x1);
    h = (u0 >> 16) | (u1 & 0xffff0000u);
    float r0 = x0 - __uint_as_float(u0 & 0xffff0000u);
    float r1 = x1 - __uint_as_float(u1 & 0xffff0000u);
    asm("cvt.rn.bf16x2.f32 %0, %1, %2;" : "=r"(l) : "f"(r1), "f"(r0));
}

__device__ __forceinline__ void split_f4(float4 v, uint2& h, uint2& l) {
    pack_split2(v.x, v.y, h.x, l.x);
    pack_split2(v.z, v.w, h.y, l.y);
}

__device__ __forceinline__ void ldsm_x4(uint32_t addr, uint32_t& r0, uint32_t& r1,
                                        uint32_t& r2, uint32_t& r3) {
    asm volatile("ldmatrix.sync.aligned.m8n8.x4.shared.b16 {%0,%1,%2,%3}, [%4];"
                 : "=r"(r0), "=r"(r1), "=r"(r2), "=r"(r3) : "r"(addr));
}
__device__ __forceinline__ void ldsm_x4_t(uint32_t addr, uint32_t& r0, uint32_t& r1,
                                          uint32_t& r2, uint32_t& r3) {
    asm volatile("ldmatrix.sync.aligned.m8n8.x4.trans.shared.b16 {%0,%1,%2,%3}, [%4];"
                 : "=r"(r0), "=r"(r1), "=r"(r2), "=r"(r3) : "r"(addr));
}

__device__ __forceinline__ void mma_bf16(float* c, const uint32_t* a,
                                         uint32_t b0, uint32_t b1) {
    asm volatile(
        "mma.sync.aligned.m16n8k16.row.col.f32.bf16.bf16.f32 "
        "{%0,%1,%2,%3},{%4,%5,%6,%7},{%8,%9},{%0,%1,%2,%3};"
        : "+f"(c[0]), "+f"(c[1]), "+f"(c[2]), "+f"(c[3])
        : "r"(a[0]), "r"(a[1]), "r"(a[2]), "r"(a[3]), "r"(b0), "r"(b1));
}

// ---------------- pre-split f32 -> bf16 hi/lo ----------------
__global__ void split_kernel(const float4* __restrict__ src, uint2* __restrict__ h,
                             uint2* __restrict__ l, int n4) {
    int i = blockIdx.x * 256 + threadIdx.x;
    if (i < n4) {
        uint2 hh, ll;
        split_f4(src[i], hh, ll);
        h[i] = hh;
        l[i] = ll;
    }
}

__global__ void split4_kernel(
    const float4* __restrict__ s0, uint2* h0, uint2* l0,
    const float4* __restrict__ s1, uint2* h1, uint2* l1,
    const float4* __restrict__ s2, uint2* h2, uint2* l2,
    const float4* __restrict__ s3, uint2* h3, uint2* l3, int n4)
{
    int z = blockIdx.z;
    const float4* s = (z == 0) ? s0 : (z == 1) ? s1 : (z == 2) ? s2 : s3;
    uint2* h = (z == 0) ? h0 : (z == 1) ? h1 : (z == 2) ? h2 : h3;
    uint2* l = (z == 0) ? l0 : (z == 1) ? l1 : (z == 2) ? l2 : l3;
    int i = blockIdx.x * 256 + threadIdx.x;
    if (i < n4) {
        uint2 hh, ll;
        split_f4(s[i], hh, ll);
        h[i] = hh;
        l[i] = ll;
    }
}

// ---------------- projection GEMM: 128x128 tile, warp 32x64, 2 CTAs/SM -------
#define PA 24
#define PB2 136
__global__ __launch_bounds__(256, 2) void gemm_qkv(
    const uint16_t* __restrict__ Ah, const uint16_t* __restrict__ Al,
    const uint16_t* __restrict__ B0h, const uint16_t* __restrict__ B0l,
    const float* __restrict__ bias0, uint16_t* o0h, uint16_t* o0l,
    const uint16_t* __restrict__ B1h, const uint16_t* __restrict__ B1l,
    const float* __restrict__ bias1, uint16_t* o1h, uint16_t* o1l,
    const uint16_t* __restrict__ B2h, const uint16_t* __restrict__ B2l,
    const float* __restrict__ bias2, uint16_t* o2h, uint16_t* o2l)
{
    const int N = 1024, K = 1024;
    int z = blockIdx.z;
    const uint16_t* Bh = (z == 0) ? B0h : (z == 1) ? B1h : B2h;
    const uint16_t* Bl = (z == 0) ? B0l : (z == 1) ? B1l : B2l;
    const float* bias  = (z == 0) ? bias0 : (z == 1) ? bias1 : bias2;
    uint16_t* outH     = (z == 0) ? o0h : (z == 1) ? o1h : o2h;
    uint16_t* outL     = (z == 0) ? o0l : (z == 1) ? o1l : o2l;

    __shared__ __align__(16) uint16_t Ash[128 * PA], Asl[128 * PA];
    __shared__ __align__(16) uint16_t Bsh[16 * PB2], Bsl[16 * PB2];

    int tid = threadIdx.x, lane = tid & 31, wid = tid >> 5;
    int rowBase = blockIdx.y * 128, colBase = blockIdx.x * 128;
    int m0 = (wid >> 1) * 32, n0 = (wid & 1) * 64;

    int ar = tid >> 1, asel = (tid & 1) * 8;
    int brow = tid >> 4, bcol = (tid & 15) * 8;

    float c[2][8][4];
    #pragma unroll
    for (int i = 0; i < 2; i++)
        #pragma unroll
        for (int j = 0; j < 8; j++)
            #pragma unroll
            for (int q = 0; q < 4; q++) c[i][j][q] = 0.f;

    uint32_t sAh = smem_u32(Ash), sAl = smem_u32(Asl);
    uint32_t sBh = smem_u32(Bsh), sBl = smem_u32(Bsl);
    uint32_t aoff = (((m0 + (lane & 15)) * PA) + (lane >> 4) * 8) * 2;
    uint32_t boff = ((((lane & 7) + ((lane >> 3) & 1) * 8) * PB2) +
                     n0 + (lane >> 4) * 8) * 2;

    size_t aRow = (size_t)(rowBase + ar) * K;

    uint4 rah, ral, rbh, rbl;
    rah = *(const uint4*)&Ah[aRow + asel];
    ral = *(const uint4*)&Al[aRow + asel];
    rbh = *(const uint4*)&Bh[(size_t)brow * N + colBase + bcol];
    rbl = *(const uint4*)&Bl[(size_t)brow * N + colBase + bcol];

    const int NK = K / 16;
    for (int ks = 0; ks < NK; ks++) {
        *(uint4*)&Ash[ar * PA + asel] = rah;
        *(uint4*)&Asl[ar * PA + asel] = ral;
        *(uint4*)&Bsh[brow * PB2 + bcol] = rbh;
        *(uint4*)&Bsl[brow * PB2 + bcol] = rbl;
        __syncthreads();

        if (ks + 1 < NK) {
            int k0 = (ks + 1) * 16;
            rah = *(const uint4*)&Ah[aRow + k0 + asel];
            ral = *(const uint4*)&Al[aRow + k0 + asel];
            rbh = *(const uint4*)&Bh[(size_t)(k0 + brow) * N + colBase + bcol];
            rbl = *(const uint4*)&Bl[(size_t)(k0 + brow) * N + colBase + bcol];
        }

        uint32_t afh[2][4], afl[2][4];
        #pragma unroll
        for (int i = 0; i < 2; i++) {
            ldsm_x4(sAh + aoff + i * 768, afh[i][0], afh[i][1], afh[i][2], afh[i][3]);
            ldsm_x4(sAl + aoff + i * 768, afl[i][0], afl[i][1], afl[i][2], afl[i][3]);
        }
        #pragma unroll
        for (int j = 0; j < 4; j++) {
            uint32_t bh0, bh1, bh2, bh3, bl0, bl1, bl2, bl3;
            ldsm_x4_t(sBh + boff + j * 32, bh0, bh1, bh2, bh3);
            ldsm_x4_t(sBl + boff + j * 32, bl0, bl1, bl2, bl3);
            #pragma unroll
            for (int i = 0; i < 2; i++) {
                mma_bf16(c[i][2 * j], afh[i], bh0, bh1);
                mma_bf16(c[i][2 * j], afh[i], bl0, bl1);
                mma_bf16(c[i][2 * j], afl[i], bh0, bh1);
                mma_bf16(c[i][2 * j + 1], afh[i], bh2, bh3);
                mma_bf16(c[i][2 * j + 1], afh[i], bl2, bl3);
                mma_bf16(c[i][2 * j + 1], afl[i], bh2, bh3);
            }
        }
        __syncthreads();
    }

    int r = lane >> 2, cl2 = (lane & 3) * 2;
    #pragma unroll
    for (int i = 0; i < 2; i++) {
        int row = rowBase + m0 + i * 16 + r;
        #pragma unroll
        for (int j = 0; j < 8; j++) {
            int col = colBase + n0 + j * 8 + cl2;
            float b0 = bias[col], b1 = bias[col + 1];
            uint32_t hh, ll;
            pack_split2(c[i][j][0] + b0, c[i][j][1] + b1, hh, ll);
            *(uint32_t*)&outH[(size_t)row * N + col] = hh;
            *(uint32_t*)&outL[(size_t)row * N + col] = ll;
            pack_split2(c[i][j][2] + b0, c[i][j][3] + b1, hh, ll);
            *(uint32_t*)&outH[(size_t)(row + 8) * N + col] = hh;
            *(uint32_t*)&outL[(size_t)(row + 8) * N + col] = ll;
        }
    }
}

__global__ __launch_bounds__(256, 2) void gemm_out(
    const uint16_t* __restrict__ Ah, const uint16_t* __restrict__ Al,
    const uint16_t* __restrict__ Bh, const uint16_t* __restrict__ Bl,
    const float* __restrict__ bias, float* __restrict__ outF)
{
    const int N = 1024, K = 1024;
    __shared__ __align__(16) uint16_t Ash[128 * PA], Asl[128 * PA];
    __shared__ __align__(16) uint16_t Bsh[16 * PB2], Bsl[16 * PB2];

    int tid = threadIdx.x, lane = tid & 31, wid = tid >> 5;
    int rowBase = blockIdx.y * 128, colBase = blockIdx.x * 128;
    int m0 = (wid >> 1) * 32, n0 = (wid & 1) * 64;

    int ar = tid >> 1, asel = (tid & 1) * 8;
    int brow = tid >> 4, bcol = (tid & 15) * 8;

    float c[2][8][4];
    #pragma unroll
    for (int i = 0; i < 2; i++)
        #pragma unroll
        for (int j = 0; j < 8; j++)
            #pragma unroll
            for (int q = 0; q < 4; q++) c[i][j][q] = 0.f;

    uint32_t sAh = smem_u32(Ash), sAl = smem_u32(Asl);
    uint32_t sBh = smem_u32(Bsh), sBl = smem_u32(Bsl);
    uint32_t aoff = (((m0 + (lane & 15)) * PA) + (lane >> 4) * 8) * 2;
    uint32_t boff = ((((lane & 7) + ((lane >> 3) & 1) * 8) * PB2) +
                     n0 + (lane >> 4) * 8) * 2;

    size_t aRow = (size_t)(rowBase + ar) * K;

    uint4 rah, ral, rbh, rbl;
    rah = *(const uint4*)&Ah[aRow + asel];
    ral = *(const uint4*)&Al[aRow + asel];
    rbh = *(const uint4*)&Bh[(size_t)brow * N + colBase + bcol];
    rbl = *(const uint4*)&Bl[(size_t)brow * N + colBase + bcol];

    const int NK = K / 16;
    for (int ks = 0; ks < NK; ks++) {
        *(uint4*)&Ash[ar * PA + asel] = rah;
        *(uint4*)&Asl[ar * PA + asel] = ral;
        *(uint4*)&Bsh[brow * PB2 + bcol] = rbh;
        *(uint4*)&Bsl[brow * PB2 + bcol] = rbl;
        __syncthreads();

        if (ks + 1 < NK) {
            int k0 = (ks + 1) * 16;
            rah = *(const uint4*)&Ah[aRow + k0 + asel];
            ral = *(const uint4*)&Al[aRow + k0 + asel];
            rbh = *(const uint4*)&Bh[(size_t)(k0 + brow) * N + colBase + bcol];
            rbl = *(const uint4*)&Bl[(size_t)(k0 + brow) * N + colBase + bcol];
        }

        uint32_t afh[2][4], afl[2][4];
        #pragma unroll
        for (int i = 0; i < 2; i++) {
            ldsm_x4(sAh + aoff + i * 768, afh[i][0], afh[i][1], afh[i][2], afh[i][3]);
            ldsm_x4(sAl + aoff + i * 768, afl[i][0], afl[i][1], afl[i][2], afl[i][3]);
        }
        #pragma unroll
        for (int j = 0; j < 4; j++) {
            uint32_t bh0, bh1, bh2, bh3, bl0, bl1, bl2, bl3;
            ldsm_x4_t(sBh + boff + j * 32, bh0, bh1, bh2, bh3);
            ldsm_x4_t(sBl + boff + j * 32, bl0, bl1, bl2, bl3);
            #pragma unroll
            for (int i = 0; i < 2; i++) {
                mma_bf16(c[i][2 * j], afh[i], bh0, bh1);
                mma_bf16(c[i][2 * j], afh[i], bl0, bl1);
                mma_bf16(c[i][2 * j], afl[i], bh0, bh1);
                mma_bf16(c[i][2 * j + 1], afh[i], bh2, bh3);
                mma_bf16(c[i][2 * j + 1], afh[i], bl2, bl3);
                mma_bf16(c[i][2 * j + 1], afl[i], bh2, bh3);
            }
        }
        __syncthreads();
    }

    int r = lane >> 2, cl2 = (lane & 3) * 2;
    #pragma unroll
    for (int i = 0; i < 2; i++) {
        int row = rowBase + m0 + i * 16 + r;
        #pragma unroll
        for (int j = 0; j < 8; j++) {
            int col = colBase + n0 + j * 8 + cl2;
            float b0 = bias[col], b1 = bias[col + 1];
            *(float2*)&outF[(size_t)row * N + col] =
                make_float2(c[i][j][0] + b0, c[i][j][1] + b1);
            *(float2*)&outF[(size_t)(row + 8) * N + col] =
                make_float2(c[i][j][2] + b0, c[i][j][3] + b1);
        }
    }
}

// ---------------- scores: 128x128 blocks, warp 32x64, 2 CTAs/SM ----------------
__global__ __launch_bounds__(256, 2) void scores_mma(
    const uint16_t* __restrict__ Qh, const uint16_t* __restrict__ Ql,
    const uint16_t* __restrict__ Kh, const uint16_t* __restrict__ Kl,
    const float* __restrict__ lsc, const float* __restrict__ gsc,
    float* __restrict__ attnL, float* __restrict__ attnG,
    float2* __restrict__ bstats)
{
    int bh = blockIdx.z;
    int b = bh >> 4, h = bh & 15;
    int rowBase = blockIdx.y * 128, colBase = blockIdx.x * 128;
    bool is_local = (h < LH);
    float* dst = is_local ? attnL + (size_t)(b * LH + h) * Ll * Ll
                          : attnG + (size_t)(b * LH + h - LH) * Ll * Ll;
    int tid = threadIdx.x;

    if (is_local && colBase > rowBase) {
        float4 z4 = make_float4(0.f, 0.f, 0.f, 0.f);
        #pragma unroll
        for (int i = 0; i < 16; i++) {
            int s = tid + i * 256;
            int row = s >> 5, c4 = s & 31;
            *(float4*)&dst[(size_t)(rowBase + row) * Ll + colBase + c4 * 4] = z4;
        }
        return;
    }
    bool diag = is_local && (colBase == rowBase);

    float scale = 0.125f * (is_local ? lsc[0] : gsc[0]);

    __shared__ __align__(16) uint16_t Ash[128 * PA], Asl[128 * PA];
    __shared__ __align__(16) uint16_t Bsh[128 * PA], Bsl[128 * PA];

    int lane = tid & 31, wid = tid >> 5;
    int m0 = (wid >> 1) * 32, n0 = (wid & 1) * 64;

    int ar = tid >> 1, asel = (tid & 1) * 8;
    size_t aRow = (size_t)(b * Ll + rowBase + ar) * Dd + h * 64;
    size_t bRow = (size_t)(b * Ll + colBase + ar) * Dd + h * 64;

    float c[2][8][4];
    #pragma unroll
    for (int i = 0; i < 2; i++)
        #pragma unroll
        for (int j = 0; j < 8; j++)
            #pragma unroll
            for (int q = 0; q < 4; q++) c[i][j][q] = 0.f;

    uint32_t sAh = smem_u32(Ash), sAl = smem_u32(Asl);
    uint32_t sBh = smem_u32(Bsh), sBl = smem_u32(Bsl);
    uint32_t aoff = (((m0 + (lane & 15)) * PA) + (lane >> 4) * 8) * 2;
    uint32_t boff = (((n0 + (lane & 7) + (lane >> 4) * 8) * PA) +
                     ((lane >> 3) & 1) * 8) * 2;

    uint4 rah, ral, rbh, rbl;
    rah = *(const uint4*)&Qh[aRow + asel];
    ral = *(const uint4*)&Ql[aRow + asel];
    rbh = *(const uint4*)&Kh[bRow + asel];
    rbl = *(const uint4*)&Kl[bRow + asel];

    const int NK = 4;
    for (int ks = 0; ks < NK; ks++) {
        *(uint4*)&Ash[ar * PA + asel] = rah;
        *(uint4*)&Asl[ar * PA + asel] = ral;
        *(uint4*)&Bsh[ar * PA + asel] = rbh;
        *(uint4*)&Bsl[ar * PA + asel] = rbl;
        __syncthreads();

        if (ks + 1 < NK) {
            int k0 = (ks + 1) * 16;
            rah = *(const uint4*)&Qh[aRow + k0 + asel];
            ral = *(const uint4*)&Ql[aRow + k0 + asel];
            rbh = *(const uint4*)&Kh[bRow + k0 + asel];
            rbl = *(const uint4*)&Kl[bRow + k0 + asel];
        }

        uint32_t afh[2][4], afl[2][4];
        #pragma unroll
        for (int i = 0; i < 2; i++) {
            ldsm_x4(sAh + aoff + i * 768, afh[i][0], afh[i][1], afh[i][2], afh[i][3]);
            ldsm_x4(sAl + aoff + i * 768, afl[i][0], afl[i][1], afl[i][2], afl[i][3]);
        }
        #pragma unroll
        for (int j = 0; j < 4; j++) {
            uint32_t bh0, bh1, bh2, bh3, bl0, bl1, bl2, bl3;
            ldsm_x4(sBh + boff + j * 768, bh0, bh1, bh2, bh3);
            ldsm_x4(sBl + boff + j * 768, bl0, bl1, bl2, bl3);
            #pragma unroll
            for (int i = 0; i < 2; i++) {
                mma_bf16(c[i][2 * j], afh[i], bh0, bh1);
                mma_bf16(c[i][2 * j], afh[i], bl0, bl1);
                mma_bf16(c[i][2 * j], afl[i], bh0, bh1);
                mma_bf16(c[i][2 * j + 1], afh[i], bh2, bh3);
                mma_bf16(c[i][2 * j + 1], afh[i], bl2, bl3);
                mma_bf16(c[i][2 * j + 1], afl[i], bh2, bh3);
            }
        }
        __syncthreads();
    }

    #pragma unroll
    for (int i = 0; i < 2; i++)
        #pragma unroll
        for (int j = 0; j < 8; j++)
            #pragma unroll
            for (int q = 0; q < 4; q++) c[i][j][q] *= scale;

    int r = lane >> 2, cl2 = (lane & 3) * 2;
    int ntile = (colBase + n0) >> 6;

    if (!diag) {
        #pragma unroll
        for (int i = 0; i < 2; i++) {
            #pragma unroll
            for (int half = 0; half < 2; half++) {
                int row = rowBase + m0 + i * 16 + r + half * 8;
                float m = -INFINITY;
                #pragma unroll
                for (int j = 0; j < 8; j++)
                    m = fmaxf(m, fmaxf(c[i][j][half * 2], c[i][j][half * 2 + 1]));
                m = fmaxf(m, __shfl_xor_sync(0xffffffffu, m, 1));
                m = fmaxf(m, __shfl_xor_sync(0xffffffffu, m, 2));
                float s = 0.f;
                #pragma unroll
                for (int j = 0; j < 8; j++) {
                    s += __expf(c[i][j][half * 2] - m);
                    s += __expf(c[i][j][half * 2 + 1] - m);
                }
                s += __shfl_xor_sync(0xffffffffu, s, 1);
                s += __shfl_xor_sync(0xffffffffu, s, 2);
                if ((lane & 3) == 0)
                    bstats[((size_t)bh * 2048 + row) * 32 + ntile] = make_float2(m, s);
                #pragma unroll
                for (int j = 0; j < 8; j++)
                    *(float2*)&dst[(size_t)row * Ll + colBase + n0 + j * 8 + cl2] =
                        make_float2(c[i][j][half * 2], c[i][j][half * 2 + 1]);
            }
        }
    } else {
        #pragma unroll
        for (int i = 0; i < 2; i++) {
            #pragma unroll
            for (int half = 0; half < 2; half++) {
                int row = rowBase + m0 + i * 16 + r + half * 8;
                float m = -INFINITY;
                #pragma unroll
                for (int j = 0; j < 8; j++) {
                    int col = colBase + n0 + j * 8 + cl2;
                    float v0 = c[i][j][half * 2], v1 = c[i][j][half * 2 + 1];
                    m = fmaxf(m, (col <= row) ? v0 : -INFINITY);
                    m = fmaxf(m, (col + 1 <= row) ? v1 : -INFINITY);
                }
                m = fmaxf(m, __shfl_xor_sync(0xffffffffu, m, 1));
                m = fmaxf(m, __shfl_xor_sync(0xffffffffu, m, 2));
                float s = 0.f;
                if (m > -1e30f) {
                    #pragma unroll
                    for (int j = 0; j < 8; j++) {
                        int col = colBase + n0 + j * 8 + cl2;
                        s += (col <= row) ? __expf(c[i][j][half * 2] - m) : 0.f;
                        s += (col + 1 <= row) ? __expf(c[i][j][half * 2 + 1] - m) : 0.f;
                    }
                }
                s += __shfl_xor_sync(0xffffffffu, s, 1);
                s += __shfl_xor_sync(0xffffffffu, s, 2);
                if ((lane & 3) == 0)
                    bstats[((size_t)bh * 2048 + row) * 32 + ntile] = make_float2(m, s);
                #pragma unroll
                for (int j = 0; j < 8; j++) {
                    int col = colBase + n0 + j * 8 + cl2;
                    float v0 = (col <= row) ? c[i][j][half * 2] : 0.f;
                    float v1 = (col + 1 <= row) ? c[i][j][half * 2 + 1] : 0.f;
                    *(float2*)&dst[(size_t)row * Ll + col] = make_float2(v0, v1);
                }
            }
        }
    }
}

// ---------------- reduce partial stats -> per-row (max, 1/Z) ----------------
__global__ void reduce_stats(const float2* __restrict__ bst, float2* __restrict__ rst) {
    int idx = blockIdx.x * 256 + threadIdx.x;
    int bh = idx >> 11, row = idx & 2047;
    bool is_local = (bh & 15) < LH;
    int jmax = is_local ? (row >> 6) : 31;
    const float2* p = &bst[(size_t)idx * 32];
    float m = -INFINITY;
    for (int j = 0; j <= jmax; j++) m = fmaxf(m, p[j].x);
    float Z = 0.f;
    for (int j = 0; j <= jmax; j++) {
        float2 v = p[j];
        if (v.x > -1e30f) Z += v.y * __expf(v.x - m);
    }
    rst[idx] = make_float2(m, 1.f / Z);
}

// ---------------- AV: chunk=64, normalize S -> P (write P), O = P @ V ----------
// dynamic smem layout (uint16 units):
//   Ash @ 0       (128*72)
//   Asl @ 9216
//   Bsh @ 18432   (64*72)
//   Bsl @ 23040
// total 27648 u16 = 55296 B
#define AV_SMEM 55296
__global__ __launch_bounds__(256, 2) void av_mma(
    float* attnL, float* attnG,
    const uint16_t* __restrict__ Vh, const uint16_t* __restrict__ Vl,
    const float2* __restrict__ rst,
    uint16_t* __restrict__ Oh, uint16_t* __restrict__ Ol)
{
    extern __shared__ __align__(16) uint16_t dsm[];
    uint16_t* Ash = dsm;
    uint16_t* Asl = dsm + 9216;
    uint16_t* Bsh = dsm + 18432;
    uint16_t* Bsl = dsm + 23040;

    int bh = blockIdx.y;
    int b = bh >> 4, h = bh & 15;
    int rowBase = blockIdx.x * 128;
    bool is_local = (h < LH);

    float* P = is_local ? attnL + (size_t)(b * LH + h) * Ll * Ll
                        : attnG + (size_t)(b * LH + h - LH) * Ll * Ll;
    int NK = (is_local ? (rowBase + 128) : Ll) / 64;
    int maskC = is_local ? (rowBase >> 6) : (1 << 30);

    int tid = threadIdx.x, lane = tid & 31, wid = tid >> 5;
    int m0 = (wid >> 1) * 32, n0 = (wid & 1) * 32;

    float c[2][4][4];
    #pragma unroll
    for (int i = 0; i < 2; i++)
        #pragma unroll
        for (int j = 0; j < 4; j++)
            #pragma unroll
            for (int q = 0; q < 4; q++) c[i][j][q] = 0.f;

    uint32_t sAh = smem_u32(Ash), sAl = smem_u32(Asl);
    uint32_t sBh = smem_u32(Bsh), sBl = smem_u32(Bsl);
    // A ldsm base: row (m), col (k within chunk)
    uint32_t aoff = (((m0 + (lane & 15)) * 72) + (lane >> 4) * 8) * 2;
    // B ldsm_t base: row (k), col (n)
    uint32_t boff = ((((lane & 7) + ((lane >> 3) & 1) * 8) * 72) +
                     n0 + (lane >> 4) * 8) * 2;

    // per-thread A staging coords (4 iters): row = s>>3, cseg = (s&7)*8
    int arow0 = tid >> 3, acseg = (tid & 7) * 8;
    // B staging: row = tid>>2, cs = (tid&3)*16
    int vrow = tid >> 2, vcs = (tid & 3) * 16;
    size_t vBase = (size_t)(b * Ll) * Dd + h * 64 + vcs;

    for (int ck = 0; ck < NK; ck++) {
        int k0 = ck * 64;
        bool needMask = (ck >= maskC);

        // stage A: normalize S -> P, write back, split into smem
        #pragma unroll
        for (int it = 0; it < 4; it++) {
            int row = arow0 + it * 32;
            int rowG = rowBase + row;
            float2 st = rst[(size_t)bh * 2048 + rowG];
            size_t base = (size_t)rowG * Ll + k0 + acseg;
            float4 v0 = *(const float4*)&P[base];
            float4 v1 = *(const float4*)&P[base + 4];
            float4 p0, p1;
            if (!needMask) {
                p0.x = __expf(v0.x - st.x) * st.y;
                p0.y = __expf(v0.y - st.x) * st.y;
                p0.z = __expf(v0.z - st.x) * st.y;
                p0.w = __expf(v0.w - st.x) * st.y;
                p1.x = __expf(v1.x - st.x) * st.y;
                p1.y = __expf(v1.y - st.x) * st.y;
                p1.z = __expf(v1.z - st.x) * st.y;
                p1.w = __expf(v1.w - st.x) * st.y;
            } else {
                int c0 = k0 + acseg;
                p0.x = (c0 + 0 <= rowG) ? __expf(v0.x - st.x) * st.y : 0.f;
                p0.y = (c0 + 1 <= rowG) ? __expf(v0.y - st.x) * st.y : 0.f;
                p0.z = (c0 + 2 <= rowG) ? __expf(v0.z - st.x) * st.y : 0.f;
                p0.w = (c0 + 3 <= rowG) ? __expf(v0.w - st.x) * st.y : 0.f;
                p1.x = (c0 + 4 <= rowG) ? __expf(v1.x - st.x) * st.y : 0.f;
                p1.y = (c0 + 5 <= rowG) ? __expf(v1.y - st.x) * st.y : 0.f;
                p1.z = (c0 + 6 <= rowG) ? __expf(v1.z - st.x) * st.y : 0.f;
                p1.w = (c0 + 7 <= rowG) ? __expf(v1.w - st.x) * st.y : 0.f;
            }
            *(float4*)&P[base] = p0;
            *(float4*)&P[base + 4] = p1;
            uint2 h0, l0, h1, l1;
            split_f4(p0, h0, l0);
            split_f4(p1, h1, l1);
            *(uint4*)&Ash[row * 72 + acseg] = make_uint4(h0.x, h0.y, h1.x, h1.y);
            *(uint4*)&Asl[row * 72 + acseg] = make_uint4(l0.x, l0.y, l1.x, l1.y);
        }
        // stage B: V chunk 64 rows x 64 cols
        {
            size_t g = vBase + (size_t)(k0 + vrow) * Dd;
            *(uint4*)&Bsh[vrow * 72 + vcs] = *(const uint4*)&Vh[g];
            *(uint4*)&Bsh[vrow * 72 + vcs + 8] = *(const uint4*)&Vh[g + 8];
            *(uint4*)&Bsl[vrow * 72 + vcs] = *(const uint4*)&Vl[g];
            *(uint4*)&Bsl[vrow * 72 + vcs + 8] = *(const uint4*)&Vl[g + 8];
        }
        __syncthreads();

        #pragma unroll
        for (int kk = 0; kk < 4; kk++) {
            uint32_t afh[2][4], afl[2][4];
            #pragma unroll
            for (int i = 0; i < 2; i++) {
                ldsm_x4(sAh + aoff + kk * 32 + i * 2304,
                        afh[i][0], afh[i][1], afh[i][2], afh[i][3]);
                ldsm_x4(sAl + aoff + kk * 32 + i * 2304,
                        afl[i][0], afl[i][1], afl[i][2], afl[i][3]);
            }
            #pragma unroll
            for (int j = 0; j < 2; j++) {
                uint32_t bh0, bh1, bh2, bh3, bl0, bl1, bl2, bl3;
                ldsm_x4_t(sBh + boff + kk * 2304 + j * 32, bh0, bh1, bh2, bh3);
                ldsm_x4_t(sBl + boff + kk * 2304 + j * 32, bl0, bl1, bl2, bl3);
                #pragma unroll
                for (int i = 0; i < 2; i++) {
                    mma_bf16(c[i][2 * j], afh[i], bh0, bh1);
                    mma_bf16(c[i][2 * j], afh[i], bl0, bl1);
                    mma_bf16(c[i][2 * j], afl[i], bh0, bh1);
                    mma_bf16(c[i][2 * j + 1], afh[i], bh2, bh3);
                    mma_bf16(c[i][2 * j + 1], afh[i], bl2, bl3);
                    mma_bf16(c[i][2 * j + 1], afl[i], bh2, bh3);
                }
            }
        }
        __syncthreads();
    }

    int r = lane >> 2, cl2 = (lane & 3) * 2;
    #pragma unroll
    for (int i = 0; i < 2; i++) {
        int row = rowBase + m0 + i * 16 + r;
        #pragma unroll
        for (int j = 0; j < 4; j++) {
            int col = n0 + j * 8 + cl2;
            size_t off0 = (size_t)(b * Ll + row) * Dd + h * 64 + col;
            size_t off1 = (size_t)(b * Ll + row + 8) * Dd + h * 64 + col;
            uint32_t hh, ll;
            pack_split2(c[i][j][0], c[i][j][1], hh, ll);
            *(uint32_t*)&Oh[off0] = hh;
            *(uint32_t*)&Ol[off0] = ll;
            pack_split2(c[i][j][2], c[i][j][3], hh, ll);
            *(uint32_t*)&Oh[off1] = hh;
            *(uint32_t*)&Ol[off1] = ll;
        }
    }
}

// ---------------- launch ----------------
extern "C" void kernel_launch(void* const* d_in, const int* in_sizes, int n_in,
                              void* d_out, int out_size)
{
    const float* x   = (const float*)d_in[0];
    const float* Wq  = (const float*)d_in[1];
    const float* bq  = (const float*)d_in[2];
    const float* Wk  = (const float*)d_in[3];
    const float* bk  = (const float*)d_in[4];
    const float* Wv  = (const float*)d_in[5];
    const float* bv  = (const float*)d_in[6];
    const float* Wo  = (const float*)d_in[7];
    const float* bo  = (const float*)d_in[8];
    const float* lsc = (const float*)d_in[9];
    const float* gsc = (const float*)d_in[10];

    float* out   = (float*)d_out;
    float* attnL = out + (size_t)MLEN * Dd;
    float* attnG = attnL + (size_t)Bb * LH * Ll * Ll;

    uint16_t *xh, *xl, *Wqh, *Wql, *Wkh, *Wkl, *Wvh, *Wvl, *Woh, *Wol;
    uint16_t *Qh, *Ql, *Kh, *Kl, *Vh, *Vl, *Ohp, *Olp;
    float2 *bst, *rstp;
    cudaGetSymbolAddress((void**)&xh, g_xh);   cudaGetSymbolAddress((void**)&xl, g_xl);
    cudaGetSymbolAddress((void**)&Wqh, g_Wqh); cudaGetSymbolAddress((void**)&Wql, g_Wql);
    cudaGetSymbolAddress((void**)&Wkh, g_Wkh); cudaGetSymbolAddress((void**)&Wkl, g_Wkl);
    cudaGetSymbolAddress((void**)&Wvh, g_Wvh); cudaGetSymbolAddress((void**)&Wvl, g_Wvl);
    cudaGetSymbolAddress((void**)&Woh, g_Woh); cudaGetSymbolAddress((void**)&Wol, g_Wol);
    cudaGetSymbolAddress((void**)&Qh, g_Qh);   cudaGetSymbolAddress((void**)&Ql, g_Ql);
    cudaGetSymbolAddress((void**)&Kh, g_Kh);   cudaGetSymbolAddress((void**)&Kl, g_Kl);
    cudaGetSymbolAddress((void**)&Vh, g_Vh);   cudaGetSymbolAddress((void**)&Vl, g_Vl);
    cudaGetSymbolAddress((void**)&Ohp, g_Oh);  cudaGetSymbolAddress((void**)&Olp, g_Ol);
    cudaGetSymbolAddress((void**)&bst, g_bstats);
    cudaGetSymbolAddress((void**)&rstp, g_rstats);

    cudaFuncSetAttribute(av_mma, cudaFuncAttributeMaxDynamicSharedMemorySize, AV_SMEM);

    int nx4 = MLEN * Dd / 4;
    int nw4 = Dd * Dd / 4;
    split_kernel<<<nx4 / 256, 256>>>((const float4*)x, (uint2*)xh, (uint2*)xl, nx4);
    split4_kernel<<<dim3(nw4 / 256, 1, 4), 256>>>(
        (const float4*)Wq, (uint2*)Wqh, (uint2*)Wql,
        (const float4*)Wk, (uint2*)Wkh, (uint2*)Wkl,
        (const float4*)Wv, (uint2*)Wvh, (uint2*)Wvl,
        (const float4*)Wo, (uint2*)Woh, (uint2*)Wol, nw4);

    gemm_qkv<<<dim3(8, 32, 3), 256>>>(xh, xl,
        Wqh, Wql, bq, Qh, Ql,
        Wkh, Wkl, bk, Kh, Kl,
        Wvh, Wvl, bv, Vh, Vl);

    scores_mma<<<dim3(16, 16, 32), 256>>>(Qh, Ql, Kh, Kl, lsc, gsc, attnL, attnG, bst);
    reduce_stats<<<256, 256>>>(bst, rstp);
    av_mma<<<dim3(16, 32), 256, AV_SMEM>>>(attnL, attnG, Vh, Vl, rstp, Ohp, Olp);

    gemm_out<<<dim3(8, 32), 256>>>(Ohp, Olp, Woh, Wol, bo, out);
}